// round 13
// baseline (speedup 1.0000x reference)
#include <cuda_runtime.h>
#include <cuda_bf16.h>
#include <math.h>
#include <stdint.h>

// ---------------------------------------------------------------------------
// FixFeatureAttention sm_103.  R13: GEMMs re-tiled to BN=64 for occupancy
// (qkv 384 CTAs, proj 256 CTAs; acc regs halved -> 2 CTAs/SM). Fusions and
// attention unchanged from R12.
// ---------------------------------------------------------------------------

#define HW 4096
#define LOG2E 1.4426950408889634f
#define QSCALE 0.17677669529663687f   // 1/sqrt(32)

__device__ float    g_ypart[2 * 256 * HW];
__device__ float    g_lpart[2 * 8 * HW];
__device__ float    g_proj[512 * HW];
__device__ uint8_t  g_tiles[6 * 1024 * 1024];
__device__ uint32_t g_posb[8 * 2048];

#define SW64R(o) ((o) ^ ((((o) >> 7) & 3) << 4))

__device__ __forceinline__ uint32_t smem_u32(const void* p) {
    uint32_t a;
    asm("{.reg .u64 t; cvta.to.shared.u64 t, %1; cvt.u32.u64 %0, t;}" : "=r"(a) : "l"(p));
    return a;
}
__device__ __forceinline__ uint32_t cvt_bf2(float hi, float lo) {
    uint32_t r;
    asm("cvt.rn.bf16x2.f32 %0, %1, %2;" : "=r"(r) : "f"(hi), "f"(lo));
    return r;
}
__device__ __forceinline__ void ldsm4(uint32_t& r0, uint32_t& r1, uint32_t& r2,
                                      uint32_t& r3, uint32_t a) {
    asm volatile("ldmatrix.sync.aligned.m8n8.x4.shared.b16 {%0,%1,%2,%3}, [%4];"
                 : "=r"(r0), "=r"(r1), "=r"(r2), "=r"(r3) : "r"(a));
}
__device__ __forceinline__ void ldsm4t(uint32_t& r0, uint32_t& r1, uint32_t& r2,
                                       uint32_t& r3, uint32_t a) {
    asm volatile("ldmatrix.sync.aligned.m8n8.x4.trans.shared.b16 {%0,%1,%2,%3}, [%4];"
                 : "=r"(r0), "=r"(r1), "=r"(r2), "=r"(r3) : "r"(a));
}
__device__ __forceinline__ void mma16816(float* c, const uint32_t* a,
                                         uint32_t b0, uint32_t b1) {
    asm("mma.sync.aligned.m16n8k16.row.col.f32.bf16.bf16.f32 "
        "{%0,%1,%2,%3},{%4,%5,%6,%7},{%8,%9},{%0,%1,%2,%3};"
        : "+f"(c[0]), "+f"(c[1]), "+f"(c[2]), "+f"(c[3])
        : "r"(a[0]), "r"(a[1]), "r"(a[2]), "r"(a[3]), "r"(b0), "r"(b1));
}
#define CP16(dst, src) asm volatile("cp.async.cg.shared.global [%0], [%1], 16;" \
                                    :: "r"(dst), "l"(src) : "memory")
#define CPCOMMIT()     asm volatile("cp.async.commit_group;" ::: "memory")
#define CPWAIT0()      asm volatile("cp.async.wait_group 0;" ::: "memory")

__device__ __forceinline__ uint32_t pexp2(uint32_t xu, uint32_t posu) {
    uint32_t x, t, u, f, p, q;
    asm("add.rn.bf16x2 %0, %1, %2;" : "=r"(x) : "r"(xu), "r"(posu));
    asm("add.rn.bf16x2 %0, %1, %2;" : "=r"(t) : "r"(x), "r"(0x43404340u));
    asm("sub.rn.bf16x2 %0, %1, %2;" : "=r"(u) : "r"(t), "r"(0x43404340u));
    asm("sub.rn.bf16x2 %0, %1, %2;" : "=r"(f) : "r"(x), "r"(u));
    asm("fma.rn.bf16x2 %0, %1, %2, %3;" : "=r"(p)
        : "r"(0x3E783E78u), "r"(f), "r"(0x3F343F34u));
    asm("fma.rn.bf16x2 %0, %1, %2, %3;" : "=r"(q)
        : "r"(p), "r"(f), "r"(0x3F803F80u));
    return (t & 0x007F007Fu) * 128u + q + 0xDFFFE000u;
}

// ----------------- pos bias bilinear 16->64, packed bf16x2 (xLOG2E) ---------
__global__ void pos_kernel(const float* __restrict__ pb, uint32_t* __restrict__ posb) {
    int i = blockIdx.x * 256 + threadIdx.x;
    if (i >= 8 * 2048) return;
    int h = i >> 11, jp = i & 2047;
    float v[2];
    #pragma unroll
    for (int s = 0; s < 2; s++) {
        int j = jp * 2 + s;
        int py = j >> 6, px = j & 63;
        float sy = (py + 0.5f) * 0.25f - 0.5f;
        float sx = (px + 0.5f) * 0.25f - 0.5f;
        float fy0 = floorf(sy), fx0 = floorf(sx);
        float wy = sy - fy0, wx = sx - fx0;
        int y0 = max((int)fy0, 0), y1 = min((int)fy0 + 1, 15);
        int x0 = max((int)fx0, 0), x1 = min((int)fx0 + 1, 15);
        const float* p = pb + h * 256;
        float v00 = p[y0 * 16 + x0], v01 = p[y0 * 16 + x1];
        float v10 = p[y1 * 16 + x0], v11 = p[y1 * 16 + x1];
        float va = v00 + (v01 - v00) * wx;
        float vb = v10 + (v11 - v10) * wx;
        v[s] = (va + (vb - va) * wy) * LOG2E;
    }
    posb[i] = cvt_bf2(v[1], v[0]);
}

// ===== qkv GEMM BN=64: C = w_qkv * x, fused bf16 tile pack epilogue =========
// grid (64, 6): bn = blockIdx.x*64 pixels, bm = blockIdx.y*128 channels.
__global__ __launch_bounds__(256) void qkv_gemm_kernel(
    const float* __restrict__ A, const float* __restrict__ B,
    uint8_t* __restrict__ tiles, int K)
{
    __shared__ __align__(128) char sA[8192];
    __shared__ __align__(128) char sB[4096];
    __shared__ __align__(16)  float sT[32][132];
    const int t = threadIdx.x, wid = t >> 5, lane = t & 31;
    const int bm = blockIdx.y * 128, bn = blockIdx.x * 64;
    const uint32_t ab = smem_u32(sA), bb = smem_u32(sB);

    const int ma = t >> 1, qa = t & 1;      // A staging
    const int nb = t & 63, kq = t >> 6;     // B staging: col(n), k-quarter

    const int fr = wid * 16 + (lane & 7) + ((lane >> 3) & 1) * 8;
    const uint32_t aA0 = ab + SW64R(fr * 64 + (lane >> 4) * 16);
    const uint32_t aA1 = ab + SW64R(fr * 64 + (2 + (lane >> 4)) * 16);
    const int br = (lane & 7) + (lane >> 4) * 8;
    const uint32_t aB0 = bb + SW64R(br * 64 + ((lane >> 3) & 1) * 16);
    const uint32_t aB1 = bb + SW64R(br * 64 + (2 + ((lane >> 3) & 1)) * 16);

    const uint32_t stA0 = ab + SW64R(ma * 64 + qa * 32);
    const uint32_t stA1 = ab + SW64R(ma * 64 + qa * 32 + 16);
    const uint32_t stB  = bb + SW64R(nb * 64 + kq * 16);

    float acc[8][4];
    #pragma unroll
    for (int i = 0; i < 8; i++)
        #pragma unroll
        for (int v = 0; v < 4; v++) acc[i][v] = 0.f;

    const int ntiles = K >> 5;
    float av[16], bv[8];

    {
        const float* ap = A + (size_t)(bm + ma) * K + qa * 16;
        #pragma unroll
        for (int i = 0; i < 4; i++) {
            float4 x = ((const float4*)ap)[i];
            av[4*i] = x.x; av[4*i+1] = x.y; av[4*i+2] = x.z; av[4*i+3] = x.w;
        }
        const float* bp = B + (size_t)(kq * 8) * HW + bn + nb;
        #pragma unroll
        for (int i = 0; i < 8; i++) bv[i] = bp[(size_t)i * HW];
        uint32_t ua[8], ub[4];
        #pragma unroll
        for (int i = 0; i < 8; i++) ua[i] = cvt_bf2(av[2*i+1], av[2*i]);
        #pragma unroll
        for (int i = 0; i < 4; i++) ub[i] = cvt_bf2(bv[2*i+1], bv[2*i]);
        asm volatile("st.shared.v4.b32 [%0], {%1,%2,%3,%4};"
                     :: "r"(stA0), "r"(ua[0]), "r"(ua[1]), "r"(ua[2]), "r"(ua[3]));
        asm volatile("st.shared.v4.b32 [%0], {%1,%2,%3,%4};"
                     :: "r"(stA1), "r"(ua[4]), "r"(ua[5]), "r"(ua[6]), "r"(ua[7]));
        asm volatile("st.shared.v4.b32 [%0], {%1,%2,%3,%4};"
                     :: "r"(stB), "r"(ub[0]), "r"(ub[1]), "r"(ub[2]), "r"(ub[3]));
    }
    __syncthreads();

    for (int kt = 0; kt < ntiles; kt++) {
        if (kt + 1 < ntiles) {
            int k0 = (kt + 1) * 32;
            const float* ap = A + (size_t)(bm + ma) * K + k0 + qa * 16;
            #pragma unroll
            for (int i = 0; i < 4; i++) {
                float4 x = ((const float4*)ap)[i];
                av[4*i] = x.x; av[4*i+1] = x.y; av[4*i+2] = x.z; av[4*i+3] = x.w;
            }
            const float* bp = B + (size_t)(k0 + kq * 8) * HW + bn + nb;
            #pragma unroll
            for (int i = 0; i < 8; i++) bv[i] = bp[(size_t)i * HW];
        }

        uint32_t A0[4], A1[4];
        ldsm4(A0[0], A0[1], A0[2], A0[3], aA0);
        ldsm4(A1[0], A1[1], A1[2], A1[3], aA1);
        #pragma unroll
        for (int nch = 0; nch < 4; nch++) {
            uint32_t b00, b01, b02, b03, b10, b11, b12, b13;
            ldsm4(b00, b01, b02, b03, aB0 + nch * 1024);
            ldsm4(b10, b11, b12, b13, aB1 + nch * 1024);
            mma16816(acc[2*nch],   A0, b00, b01);
            mma16816(acc[2*nch],   A1, b10, b11);
            mma16816(acc[2*nch+1], A0, b02, b03);
            mma16816(acc[2*nch+1], A1, b12, b13);
        }
        __syncthreads();
        if (kt + 1 < ntiles) {
            uint32_t ua[8], ub[4];
            #pragma unroll
            for (int i = 0; i < 8; i++) ua[i] = cvt_bf2(av[2*i+1], av[2*i]);
            #pragma unroll
            for (int i = 0; i < 4; i++) ub[i] = cvt_bf2(bv[2*i+1], bv[2*i]);
            asm volatile("st.shared.v4.b32 [%0], {%1,%2,%3,%4};"
                         :: "r"(stA0), "r"(ua[0]), "r"(ua[1]), "r"(ua[2]), "r"(ua[3]));
            asm volatile("st.shared.v4.b32 [%0], {%1,%2,%3,%4};"
                         :: "r"(stA1), "r"(ua[4]), "r"(ua[5]), "r"(ua[6]), "r"(ua[7]));
            asm volatile("st.shared.v4.b32 [%0], {%1,%2,%3,%4};"
                         :: "r"(stB), "r"(ub[0]), "r"(ub[1]), "r"(ub[2]), "r"(ub[3]));
        }
        __syncthreads();
    }

    // ---- fused pack epilogue: 2 chunks of 32 pixels (64-pixel half tile) ----
    const int g2 = lane >> 2, q2 = lane & 3;
    const int chA = wid * 16 + g2;
    const int type = bm >> 8;
    const float esc = (type == 0) ? (QSCALE * LOG2E) : 1.0f;
    const int jb = blockIdx.x >> 1;
    const int poff = (blockIdx.x & 1) * 64;
    uint8_t* tbase = tiles + (size_t)(type * 8) * 32 * 8192 + (size_t)jb * 8192;

    #pragma unroll
    for (int p0 = 0; p0 < 64; p0 += 32) {
        __syncthreads();
        #pragma unroll
        for (int t2 = 0; t2 < 4; t2++) {
            int nc  = (p0 >> 3) + t2;
            int pxl = nc * 8 + q2 * 2 - p0;
            sT[pxl][chA]         = acc[nc][0];
            sT[pxl + 1][chA]     = acc[nc][1];
            sT[pxl][chA + 8]     = acc[nc][2];
            sT[pxl + 1][chA + 8] = acc[nc][3];
        }
        __syncthreads();
        int pxl = t >> 3;
        int pixrow = poff + p0 + pxl;
        #pragma unroll
        for (int s = 0; s < 2; s++) {
            int w = (t & 7) + s * 8;
            int hh = ((bm & 255) >> 5) + (w >> 2);
            int d0 = (w & 3) * 8;
            float4 f0 = *(float4*)&sT[pxl][w * 8];
            float4 f1 = *(float4*)&sT[pxl][w * 8 + 4];
            uint32_t b0 = cvt_bf2(f0.y * esc, f0.x * esc);
            uint32_t b1 = cvt_bf2(f0.w * esc, f0.z * esc);
            uint32_t b2 = cvt_bf2(f1.y * esc, f1.x * esc);
            uint32_t b3 = cvt_bf2(f1.w * esc, f1.z * esc);
            uint8_t* blob = tbase + (size_t)hh * 32 * 8192;
            *(uint4*)(blob + SW64R(pixrow * 64 + d0 * 2)) = make_uint4(b0, b1, b2, b3);
        }
    }
}

// ====== flash attention, split-K (unchanged, verified) ======================
__global__ __launch_bounds__(128, 4) void attn_kernel(
    const uint8_t* __restrict__ tiles, const uint32_t* __restrict__ posb,
    float* __restrict__ ypart, float* __restrict__ lpart)
{
    __shared__ __align__(128) char sQ[8192];
    __shared__ __align__(128) char sK[16384];
    __shared__ __align__(128) char sV[16384];
    __shared__ __align__(16)  char sPos[512];

    const int tid  = threadIdx.x;
    const int wid  = tid >> 5;
    const int lane = tid & 31;
    const int g    = lane >> 2;
    const int c    = lane & 3;
    const int h    = blockIdx.y;
    const int q0   = blockIdx.x * 128;
    const int z    = blockIdx.z;
    const int tb   = z * 16;

    const uint32_t qb = smem_u32(sQ), kb = smem_u32(sK), vb = smem_u32(sV);
    const uint32_t pbs = smem_u32(sPos);

    const uint8_t* tQ = tiles + (size_t)(h * 32 + blockIdx.x) * 8192;
    const uint8_t* tK = tiles + (size_t)((8 + h) * 32 + tb) * 8192;
    const uint8_t* tV = tiles + (size_t)((16 + h) * 32 + tb) * 8192;
    const uint8_t* tP = (const uint8_t*)(posb + h * 2048) + (size_t)tb * 256;

    {
        uint32_t o = tid << 4;
        #pragma unroll
        for (int s = 0; s < 4; s++) {
            CP16(qb + o + s * 2048, tQ + o + s * 2048);
            CP16(kb + o + s * 2048, tK + o + s * 2048);
            CP16(vb + o + s * 2048, tV + o + s * 2048);
        }
        if (tid < 16) CP16(pbs + (tid << 4), tP + (tid << 4));
        CPCOMMIT();
        CPWAIT0();
    }
    __syncthreads();

    uint32_t QAa0[4], QAa1[4], QAb0[4], QAb1[4];
    {
        int rowa = wid * 32 + (lane & 7) + ((lane >> 3) & 1) * 8;
        int ch   = lane >> 4;
        ldsm4(QAa0[0], QAa0[1], QAa0[2], QAa0[3], qb + SW64R(rowa * 64 + ch * 16));
        ldsm4(QAa1[0], QAa1[1], QAa1[2], QAa1[3], qb + SW64R(rowa * 64 + (2 + ch) * 16));
        int rowb = rowa + 16;
        ldsm4(QAb0[0], QAb0[1], QAb0[2], QAb0[3], qb + SW64R(rowb * 64 + ch * 16));
        ldsm4(QAb1[0], QAb1[1], QAb1[2], QAb1[3], qb + SW64R(rowb * 64 + (2 + ch) * 16));
    }
    uint32_t aK0, aK1, aV0, aV1;
    {
        int ko = (lane & 7) + (lane >> 4) * 8;
        int ch = (lane >> 3) & 1;
        aK0 = kb + SW64R(ko * 64 + ch * 16);
        aK1 = kb + SW64R(ko * 64 + (2 + ch) * 16);
    }
    {
        int ko = (lane & 7) + ((lane >> 3) & 1) * 8;
        int ch = lane >> 4;
        aV0 = vb + SW64R(ko * 64 + ch * 16);
        aV1 = vb + SW64R(ko * 64 + (2 + ch) * 16);
    }

    const uint32_t bOne = (lane < 4) ? 0x3F803F80u : 0u;
    float Ya[4][4], Yb[4][4], Ysa[4], Ysb[4];
    #pragma unroll
    for (int u = 0; u < 4; u++) {
        Ysa[u] = 0.f; Ysb[u] = 0.f;
        #pragma unroll
        for (int v = 0; v < 4; v++) { Ya[u][v] = 0.f; Yb[u][v] = 0.f; }
    }

    uint32_t kf[2][8];

    for (int it = 0; it < 16; it++) {
        const uint32_t bofs = (uint32_t)(it & 1) * 8192;

        if (it < 15) {
            const uint32_t nofs = (uint32_t)((it + 1) & 1) * 8192;
            const size_t jo = (size_t)(it + 1) * 8192;
            uint32_t o = tid << 4;
            #pragma unroll
            for (int s = 0; s < 4; s++) {
                CP16(kb + nofs + o + s * 2048, tK + jo + o + s * 2048);
                CP16(vb + nofs + o + s * 2048, tV + jo + o + s * 2048);
            }
            if (tid < 16)
                CP16(pbs + (((it + 1) & 1) << 8) + (tid << 4),
                     tP + (size_t)(it + 1) * 256 + (tid << 4));
            CPCOMMIT();
        }

        const uint32_t kA0 = aK0 + bofs, kA1 = aK1 + bofs;
        const uint32_t vA0 = aV0 + bofs, vA1 = aV1 + bofs;
        const uint32_t* sp = (const uint32_t*)(sPos + (it & 1) * 256);

        ldsm4(kf[0][0], kf[0][1], kf[0][2], kf[0][3], kA0);
        ldsm4(kf[0][4], kf[0][5], kf[0][6], kf[0][7], kA1);

        #pragma unroll
        for (int j = 0; j < 8; j++) {
            const uint32_t* kc = kf[j & 1];
            uint32_t* kn = kf[(j + 1) & 1];

            uint32_t pos0 = sp[j * 8 + c];
            uint32_t pos1 = sp[j * 8 + 4 + c];

            uint32_t v0, v1, v2, v3, w0, w1, w2, w3;
            ldsm4t(v0, v1, v2, v3, vA0 + j * 1024);
            ldsm4t(w0, w1, w2, w3, vA1 + j * 1024);
            if (j < 7) {
                ldsm4(kn[0], kn[1], kn[2], kn[3], kA0 + (j + 1) * 1024);
                ldsm4(kn[4], kn[5], kn[6], kn[7], kA1 + (j + 1) * 1024);
            }

            float Ca0[4] = {0.f,0.f,0.f,0.f}, Ca1[4] = {0.f,0.f,0.f,0.f};
            float Cb0[4] = {0.f,0.f,0.f,0.f}, Cb1[4] = {0.f,0.f,0.f,0.f};
            mma16816(Ca0, QAa0, kc[0], kc[1]);
            mma16816(Ca0, QAa1, kc[4], kc[5]);
            mma16816(Ca1, QAa0, kc[2], kc[3]);
            mma16816(Ca1, QAa1, kc[6], kc[7]);
            mma16816(Cb0, QAb0, kc[0], kc[1]);
            mma16816(Cb0, QAb1, kc[4], kc[5]);
            mma16816(Cb1, QAb0, kc[2], kc[3]);
            mma16816(Cb1, QAb1, kc[6], kc[7]);

            uint32_t Pa[4], Pb[4];
            Pa[0] = pexp2(cvt_bf2(Ca0[1], Ca0[0]), pos0);
            Pa[1] = pexp2(cvt_bf2(Ca0[3], Ca0[2]), pos0);
            Pa[2] = pexp2(cvt_bf2(Ca1[1], Ca1[0]), pos1);
            Pa[3] = pexp2(cvt_bf2(Ca1[3], Ca1[2]), pos1);
            Pb[0] = pexp2(cvt_bf2(Cb0[1], Cb0[0]), pos0);
            Pb[1] = pexp2(cvt_bf2(Cb0[3], Cb0[2]), pos0);
            Pb[2] = pexp2(cvt_bf2(Cb1[1], Cb1[0]), pos1);
            Pb[3] = pexp2(cvt_bf2(Cb1[3], Cb1[2]), pos1);

            mma16816(Ya[0], Pa, v0, v1);
            mma16816(Ya[1], Pa, v2, v3);
            mma16816(Ya[2], Pa, w0, w1);
            mma16816(Ya[3], Pa, w2, w3);
            mma16816(Ysa,   Pa, bOne, bOne);
            mma16816(Yb[0], Pb, v0, v1);
            mma16816(Yb[1], Pb, v2, v3);
            mma16816(Yb[2], Pb, w0, w1);
            mma16816(Yb[3], Pb, w2, w3);
            mma16816(Ysb,   Pb, bOne, bOne);
        }

        if (it < 15) CPWAIT0();
        __syncthreads();
    }

    float* yp = ypart + (size_t)z * 256 * HW;
    float* lp = lpart + (size_t)z * 8 * HW;
    int rowa = q0 + wid * 32 + g;
    int rowb = rowa + 16;
    #pragma unroll
    for (int v = 0; v < 4; v++) {
        int d = h * 32 + v * 8 + 2 * c;
        yp[(size_t)d * HW + rowa]           = Ya[v][0];
        yp[(size_t)(d + 1) * HW + rowa]     = Ya[v][1];
        yp[(size_t)d * HW + rowa + 8]       = Ya[v][2];
        yp[(size_t)(d + 1) * HW + rowa + 8] = Ya[v][3];
        yp[(size_t)d * HW + rowb]           = Yb[v][0];
        yp[(size_t)(d + 1) * HW + rowb]     = Yb[v][1];
        yp[(size_t)d * HW + rowb + 8]       = Yb[v][2];
        yp[(size_t)(d + 1) * HW + rowb + 8] = Yb[v][3];
    }
    if (c == 0) {
        lp[(size_t)h * HW + rowa]      = Ysa[0];
        lp[(size_t)h * HW + rowa + 8]  = Ysa[2];
        lp[(size_t)h * HW + rowb]      = Ysb[0];
        lp[(size_t)h * HW + rowb + 8]  = Ysb[2];
    }
}

// ===== proj GEMM BN=64 with fused combine ===================================
// grid (64, 4): bn = blockIdx.x*64 pixels, bm = blockIdx.y*128 out channels.
__global__ __launch_bounds__(256) void proj_gemm_kernel(
    const float* __restrict__ A, const float* __restrict__ ypart,
    const float* __restrict__ lpart, const float* __restrict__ bias,
    float* __restrict__ C, int N, int K)
{
    __shared__ __align__(128) char sA[8192];
    __shared__ __align__(128) char sB[4096];
    const int t = threadIdx.x, wid = t >> 5, lane = t & 31;
    const int bm = blockIdx.y * 128, bn = blockIdx.x * 64;
    const uint32_t ab = smem_u32(sA), bb = smem_u32(sB);

    const int ma = t >> 1, qa = t & 1;
    const int nb = t & 63, kq = t >> 6;

    const int fr = wid * 16 + (lane & 7) + ((lane >> 3) & 1) * 8;
    const uint32_t aA0 = ab + SW64R(fr * 64 + (lane >> 4) * 16);
    const uint32_t aA1 = ab + SW64R(fr * 64 + (2 + (lane >> 4)) * 16);
    const int br = (lane & 7) + (lane >> 4) * 8;
    const uint32_t aB0 = bb + SW64R(br * 64 + ((lane >> 3) & 1) * 16);
    const uint32_t aB1 = bb + SW64R(br * 64 + (2 + ((lane >> 3) & 1)) * 16);

    const uint32_t stA0 = ab + SW64R(ma * 64 + qa * 32);
    const uint32_t stA1 = ab + SW64R(ma * 64 + qa * 32 + 16);
    const uint32_t stB  = bb + SW64R(nb * 64 + kq * 16);

    const float* yp0 = ypart;
    const float* yp1 = ypart + 256 * HW;
    const float* l0  = lpart;
    const float* l1  = lpart + 8 * HW;
    const int n = bn + nb;

    float acc[8][4];
    #pragma unroll
    for (int i = 0; i < 8; i++)
        #pragma unroll
        for (int v = 0; v < 4; v++) acc[i][v] = 0.f;

    const int ntiles = K >> 5;
    float av[16], bv[8];

    {
        const float* ap = A + (size_t)(bm + ma) * K + qa * 16;
        #pragma unroll
        for (int i = 0; i < 4; i++) {
            float4 x = ((const float4*)ap)[i];
            av[4*i] = x.x; av[4*i+1] = x.y; av[4*i+2] = x.z; av[4*i+3] = x.w;
        }
        int o0 = kq * 8;
        int hh = o0 >> 5;
        float rl = 1.f / (l0[(size_t)hh * HW + n] + l1[(size_t)hh * HW + n]);
        #pragma unroll
        for (int i = 0; i < 8; i++)
            bv[i] = (yp0[(size_t)(o0 + i) * HW + n] + yp1[(size_t)(o0 + i) * HW + n]) * rl;
        uint32_t ua[8], ub[4];
        #pragma unroll
        for (int i = 0; i < 8; i++) ua[i] = cvt_bf2(av[2*i+1], av[2*i]);
        #pragma unroll
        for (int i = 0; i < 4; i++) ub[i] = cvt_bf2(bv[2*i+1], bv[2*i]);
        asm volatile("st.shared.v4.b32 [%0], {%1,%2,%3,%4};"
                     :: "r"(stA0), "r"(ua[0]), "r"(ua[1]), "r"(ua[2]), "r"(ua[3]));
        asm volatile("st.shared.v4.b32 [%0], {%1,%2,%3,%4};"
                     :: "r"(stA1), "r"(ua[4]), "r"(ua[5]), "r"(ua[6]), "r"(ua[7]));
        asm volatile("st.shared.v4.b32 [%0], {%1,%2,%3,%4};"
                     :: "r"(stB), "r"(ub[0]), "r"(ub[1]), "r"(ub[2]), "r"(ub[3]));
    }
    __syncthreads();

    for (int kt = 0; kt < ntiles; kt++) {
        if (kt + 1 < ntiles) {
            int k0 = (kt + 1) * 32;
            const float* ap = A + (size_t)(bm + ma) * K + k0 + qa * 16;
            #pragma unroll
            for (int i = 0; i < 4; i++) {
                float4 x = ((const float4*)ap)[i];
                av[4*i] = x.x; av[4*i+1] = x.y; av[4*i+2] = x.z; av[4*i+3] = x.w;
            }
            int o0 = k0 + kq * 8;
            int hh = o0 >> 5;
            float rl = 1.f / (l0[(size_t)hh * HW + n] + l1[(size_t)hh * HW + n]);
            #pragma unroll
            for (int i = 0; i < 8; i++)
                bv[i] = (yp0[(size_t)(o0 + i) * HW + n] + yp1[(size_t)(o0 + i) * HW + n]) * rl;
        }

        uint32_t A0[4], A1[4];
        ldsm4(A0[0], A0[1], A0[2], A0[3], aA0);
        ldsm4(A1[0], A1[1], A1[2], A1[3], aA1);
        #pragma unroll
        for (int nch = 0; nch < 4; nch++) {
            uint32_t b00, b01, b02, b03, b10, b11, b12, b13;
            ldsm4(b00, b01, b02, b03, aB0 + nch * 1024);
            ldsm4(b10, b11, b12, b13, aB1 + nch * 1024);
            mma16816(acc[2*nch],   A0, b00, b01);
            mma16816(acc[2*nch],   A1, b10, b11);
            mma16816(acc[2*nch+1], A0, b02, b03);
            mma16816(acc[2*nch+1], A1, b12, b13);
        }
        __syncthreads();
        if (kt + 1 < ntiles) {
            uint32_t ua[8], ub[4];
            #pragma unroll
            for (int i = 0; i < 8; i++) ua[i] = cvt_bf2(av[2*i+1], av[2*i]);
            #pragma unroll
            for (int i = 0; i < 4; i++) ub[i] = cvt_bf2(bv[2*i+1], bv[2*i]);
            asm volatile("st.shared.v4.b32 [%0], {%1,%2,%3,%4};"
                         :: "r"(stA0), "r"(ua[0]), "r"(ua[1]), "r"(ua[2]), "r"(ua[3]));
            asm volatile("st.shared.v4.b32 [%0], {%1,%2,%3,%4};"
                         :: "r"(stA1), "r"(ua[4]), "r"(ua[5]), "r"(ua[6]), "r"(ua[7]));
            asm volatile("st.shared.v4.b32 [%0], {%1,%2,%3,%4};"
                         :: "r"(stB), "r"(ub[0]), "r"(ub[1]), "r"(ub[2]), "r"(ub[3]));
        }
        __syncthreads();
    }

    int r0 = bm + wid * 16 + (lane >> 2);
    float bv0 = bias[r0];
    float bv1 = bias[r0 + 8];
    float* c0p = C + (size_t)r0 * N + bn + (lane & 3) * 2;
    float* c1p = C + (size_t)(r0 + 8) * N + bn + (lane & 3) * 2;
    #pragma unroll
    for (int nc = 0; nc < 8; nc++) {
        *(float2*)(c0p + nc * 8) = make_float2(acc[nc][0] + bv0, acc[nc][1] + bv0);
        *(float2*)(c1p + nc * 8) = make_float2(acc[nc][2] + bv1, acc[nc][3] + bv1);
    }
}

// --------------- residual + channel LayerNorm (z cached in regs) ------------
__global__ __launch_bounds__(256) void ln_kernel(
    const float* __restrict__ x, const float* __restrict__ yp,
    const float* __restrict__ gamma, const float* __restrict__ beta,
    float* __restrict__ out)
{
    __shared__ float ssum[8][32], ssq[8][32];
    int nx = threadIdx.x & 31;
    int cg = threadIdx.x >> 5;
    int n  = blockIdx.x * 32 + nx;

    float z[64];
    float sum = 0.f, sq = 0.f;
    #pragma unroll
    for (int i = 0; i < 64; i++) {
        int c = cg + i * 8;
        z[i] = x[(size_t)c * HW + n] + yp[(size_t)c * HW + n];
        sum += z[i]; sq += z[i] * z[i];
    }
    ssum[cg][nx] = sum; ssq[cg][nx] = sq;
    __syncthreads();
    float tot = 0.f, totsq = 0.f;
    #pragma unroll
    for (int g = 0; g < 8; g++) { tot += ssum[g][nx]; totsq += ssq[g][nx]; }
    float mu   = tot * (1.f / 512.f);
    float var  = totsq * (1.f / 512.f) - mu * mu;
    float rstd = rsqrtf(var + 1e-5f);
    #pragma unroll
    for (int i = 0; i < 64; i++) {
        int c = cg + i * 8;
        out[(size_t)c * HW + n] = (z[i] - mu) * rstd * gamma[c] + beta[c];
    }
}

// -----------------------------------------------------------------------------
extern "C" void kernel_launch(void* const* d_in, const int* in_sizes, int n_in,
                              void* d_out, int out_size) {
    const float* x        = (const float*)d_in[0];
    const float* w_qkv    = (const float*)d_in[1];
    const float* w_proj   = (const float*)d_in[2];
    const float* b_proj   = (const float*)d_in[3];
    const float* pos_bias = (const float*)d_in[4];
    const float* gamma    = (const float*)d_in[5];
    const float* beta     = (const float*)d_in[6];
    float* out = (float*)d_out;

    float *proj, *ypart, *lpart;
    uint8_t* tiles;
    uint32_t* posb;
    cudaGetSymbolAddress((void**)&proj,  g_proj);
    cudaGetSymbolAddress((void**)&ypart, g_ypart);
    cudaGetSymbolAddress((void**)&lpart, g_lpart);
    cudaGetSymbolAddress((void**)&tiles, g_tiles);
    cudaGetSymbolAddress((void**)&posb,  g_posb);

    pos_kernel<<<64, 256>>>(pos_bias, posb);
    qkv_gemm_kernel<<<dim3(64, 6), 256>>>(w_qkv, x, tiles, 512);
    attn_kernel<<<dim3(32, 8, 2), 128>>>(tiles, posb, ypart, lpart);
    proj_gemm_kernel<<<dim3(64, 4), 256>>>(w_proj, ypart, lpart, b_proj, proj,
                                           HW, 256);
    ln_kernel<<<128, 256>>>(x, proj, gamma, beta, out);
}

// round 14
// speedup vs baseline: 1.0543x; 1.0543x over previous
#include <cuda_runtime.h>
#include <cuda_bf16.h>
#include <math.h>
#include <stdint.h>

// ---------------------------------------------------------------------------
// FixFeatureAttention sm_103.  R14: R12 base (BN=128 GEMMs, split-K attn) +
// combine_tiles kernel producing normalized bf16 swizzled y-tiles, and proj
// GEMM B-staging via cp.async of those tiles (no strided LDG in mainloop).
// ---------------------------------------------------------------------------

#define HW 4096
#define LOG2E 1.4426950408889634f
#define QSCALE 0.17677669529663687f   // 1/sqrt(32)

__device__ float    g_ypart[2 * 256 * HW];
__device__ float    g_lpart[2 * 8 * HW];
__device__ float    g_proj[512 * HW];
__device__ uint8_t  g_tiles[6 * 1024 * 1024];   // q/k/v bf16 swizzled tiles
__device__ uint8_t  g_ytiles[2 * 1024 * 1024];  // normalized y bf16 tiles
__device__ uint32_t g_posb[8 * 2048];

#define SW64R(o) ((o) ^ ((((o) >> 7) & 3) << 4))

__device__ __forceinline__ uint32_t smem_u32(const void* p) {
    uint32_t a;
    asm("{.reg .u64 t; cvta.to.shared.u64 t, %1; cvt.u32.u64 %0, t;}" : "=r"(a) : "l"(p));
    return a;
}
__device__ __forceinline__ uint32_t cvt_bf2(float hi, float lo) {
    uint32_t r;
    asm("cvt.rn.bf16x2.f32 %0, %1, %2;" : "=r"(r) : "f"(hi), "f"(lo));
    return r;
}
__device__ __forceinline__ void ldsm4(uint32_t& r0, uint32_t& r1, uint32_t& r2,
                                      uint32_t& r3, uint32_t a) {
    asm volatile("ldmatrix.sync.aligned.m8n8.x4.shared.b16 {%0,%1,%2,%3}, [%4];"
                 : "=r"(r0), "=r"(r1), "=r"(r2), "=r"(r3) : "r"(a));
}
__device__ __forceinline__ void ldsm4t(uint32_t& r0, uint32_t& r1, uint32_t& r2,
                                       uint32_t& r3, uint32_t a) {
    asm volatile("ldmatrix.sync.aligned.m8n8.x4.trans.shared.b16 {%0,%1,%2,%3}, [%4];"
                 : "=r"(r0), "=r"(r1), "=r"(r2), "=r"(r3) : "r"(a));
}
__device__ __forceinline__ void mma16816(float* c, const uint32_t* a,
                                         uint32_t b0, uint32_t b1) {
    asm("mma.sync.aligned.m16n8k16.row.col.f32.bf16.bf16.f32 "
        "{%0,%1,%2,%3},{%4,%5,%6,%7},{%8,%9},{%0,%1,%2,%3};"
        : "+f"(c[0]), "+f"(c[1]), "+f"(c[2]), "+f"(c[3])
        : "r"(a[0]), "r"(a[1]), "r"(a[2]), "r"(a[3]), "r"(b0), "r"(b1));
}
#define CP16(dst, src) asm volatile("cp.async.cg.shared.global [%0], [%1], 16;" \
                                    :: "r"(dst), "l"(src) : "memory")
#define CPCOMMIT()     asm volatile("cp.async.commit_group;" ::: "memory")
#define CPWAIT0()      asm volatile("cp.async.wait_group 0;" ::: "memory")

__device__ __forceinline__ uint32_t pexp2(uint32_t xu, uint32_t posu) {
    uint32_t x, t, u, f, p, q;
    asm("add.rn.bf16x2 %0, %1, %2;" : "=r"(x) : "r"(xu), "r"(posu));
    asm("add.rn.bf16x2 %0, %1, %2;" : "=r"(t) : "r"(x), "r"(0x43404340u));
    asm("sub.rn.bf16x2 %0, %1, %2;" : "=r"(u) : "r"(t), "r"(0x43404340u));
    asm("sub.rn.bf16x2 %0, %1, %2;" : "=r"(f) : "r"(x), "r"(u));
    asm("fma.rn.bf16x2 %0, %1, %2, %3;" : "=r"(p)
        : "r"(0x3E783E78u), "r"(f), "r"(0x3F343F34u));
    asm("fma.rn.bf16x2 %0, %1, %2, %3;" : "=r"(q)
        : "r"(p), "r"(f), "r"(0x3F803F80u));
    return (t & 0x007F007Fu) * 128u + q + 0xDFFFE000u;
}

// ----------------- pos bias bilinear 16->64, packed bf16x2 (xLOG2E) ---------
__global__ void pos_kernel(const float* __restrict__ pb, uint32_t* __restrict__ posb) {
    int i = blockIdx.x * 256 + threadIdx.x;
    if (i >= 8 * 2048) return;
    int h = i >> 11, jp = i & 2047;
    float v[2];
    #pragma unroll
    for (int s = 0; s < 2; s++) {
        int j = jp * 2 + s;
        int py = j >> 6, px = j & 63;
        float sy = (py + 0.5f) * 0.25f - 0.5f;
        float sx = (px + 0.5f) * 0.25f - 0.5f;
        float fy0 = floorf(sy), fx0 = floorf(sx);
        float wy = sy - fy0, wx = sx - fx0;
        int y0 = max((int)fy0, 0), y1 = min((int)fy0 + 1, 15);
        int x0 = max((int)fx0, 0), x1 = min((int)fx0 + 1, 15);
        const float* p = pb + h * 256;
        float v00 = p[y0 * 16 + x0], v01 = p[y0 * 16 + x1];
        float v10 = p[y1 * 16 + x0], v11 = p[y1 * 16 + x1];
        float va = v00 + (v01 - v00) * wx;
        float vb = v10 + (v11 - v10) * wx;
        v[s] = (va + (vb - va) * wy) * LOG2E;
    }
    posb[i] = cvt_bf2(v[1], v[0]);
}

// ============ qkv GEMM (R12): C = w_qkv * x, fused bf16 tile pack ===========
__global__ __launch_bounds__(256) void qkv_gemm_kernel(
    const float* __restrict__ A, const float* __restrict__ B,
    uint8_t* __restrict__ tiles, int K)
{
    __shared__ __align__(128) char sA[8192];
    __shared__ __align__(128) char sB[8192];
    __shared__ __align__(16)  float sT[32][132];
    const int t = threadIdx.x, wid = t >> 5, lane = t & 31;
    const int bm = blockIdx.y * 128, bn = blockIdx.x * 128;
    const uint32_t ab = smem_u32(sA), bb = smem_u32(sB);

    const int ma = t >> 1, qa = t & 1;
    const int nb = t & 127, kh = t >> 7;

    const int fr = wid * 16 + (lane & 7) + ((lane >> 3) & 1) * 8;
    const uint32_t aA0 = ab + SW64R(fr * 64 + (lane >> 4) * 16);
    const uint32_t aA1 = ab + SW64R(fr * 64 + (2 + (lane >> 4)) * 16);
    const int br = (lane & 7) + (lane >> 4) * 8;
    const uint32_t aB0 = bb + SW64R(br * 64 + ((lane >> 3) & 1) * 16);
    const uint32_t aB1 = bb + SW64R(br * 64 + (2 + ((lane >> 3) & 1)) * 16);

    const uint32_t stA0 = ab + SW64R(ma * 64 + qa * 32);
    const uint32_t stA1 = ab + SW64R(ma * 64 + qa * 32 + 16);
    const uint32_t stB0 = bb + SW64R(nb * 64 + kh * 32);
    const uint32_t stB1 = bb + SW64R(nb * 64 + kh * 32 + 16);

    float acc[16][4];
    #pragma unroll
    for (int i = 0; i < 16; i++)
        #pragma unroll
        for (int v = 0; v < 4; v++) acc[i][v] = 0.f;

    const int ntiles = K >> 5;
    float av[16], bv[16];

    {
        const float* ap = A + (size_t)(bm + ma) * K + qa * 16;
        #pragma unroll
        for (int i = 0; i < 4; i++) {
            float4 x = ((const float4*)ap)[i];
            av[4*i] = x.x; av[4*i+1] = x.y; av[4*i+2] = x.z; av[4*i+3] = x.w;
        }
        const float* bp = B + (size_t)(kh * 16) * HW + bn + nb;
        #pragma unroll
        for (int i = 0; i < 16; i++) bv[i] = bp[(size_t)i * HW];
        uint32_t ua[8], ub[8];
        #pragma unroll
        for (int i = 0; i < 8; i++) {
            ua[i] = cvt_bf2(av[2*i+1], av[2*i]);
            ub[i] = cvt_bf2(bv[2*i+1], bv[2*i]);
        }
        asm volatile("st.shared.v4.b32 [%0], {%1,%2,%3,%4};"
                     :: "r"(stA0), "r"(ua[0]), "r"(ua[1]), "r"(ua[2]), "r"(ua[3]));
        asm volatile("st.shared.v4.b32 [%0], {%1,%2,%3,%4};"
                     :: "r"(stA1), "r"(ua[4]), "r"(ua[5]), "r"(ua[6]), "r"(ua[7]));
        asm volatile("st.shared.v4.b32 [%0], {%1,%2,%3,%4};"
                     :: "r"(stB0), "r"(ub[0]), "r"(ub[1]), "r"(ub[2]), "r"(ub[3]));
        asm volatile("st.shared.v4.b32 [%0], {%1,%2,%3,%4};"
                     :: "r"(stB1), "r"(ub[4]), "r"(ub[5]), "r"(ub[6]), "r"(ub[7]));
    }
    __syncthreads();

    for (int kt = 0; kt < ntiles; kt++) {
        if (kt + 1 < ntiles) {
            int k0 = (kt + 1) * 32;
            const float* ap = A + (size_t)(bm + ma) * K + k0 + qa * 16;
            #pragma unroll
            for (int i = 0; i < 4; i++) {
                float4 x = ((const float4*)ap)[i];
                av[4*i] = x.x; av[4*i+1] = x.y; av[4*i+2] = x.z; av[4*i+3] = x.w;
            }
            const float* bp = B + (size_t)(k0 + kh * 16) * HW + bn + nb;
            #pragma unroll
            for (int i = 0; i < 16; i++) bv[i] = bp[(size_t)i * HW];
        }

        uint32_t A0[4], A1[4];
        ldsm4(A0[0], A0[1], A0[2], A0[3], aA0);
        ldsm4(A1[0], A1[1], A1[2], A1[3], aA1);
        #pragma unroll
        for (int nch = 0; nch < 8; nch++) {
            uint32_t b00, b01, b02, b03, b10, b11, b12, b13;
            ldsm4(b00, b01, b02, b03, aB0 + nch * 1024);
            ldsm4(b10, b11, b12, b13, aB1 + nch * 1024);
            mma16816(acc[2*nch],   A0, b00, b01);
            mma16816(acc[2*nch],   A1, b10, b11);
            mma16816(acc[2*nch+1], A0, b02, b03);
            mma16816(acc[2*nch+1], A1, b12, b13);
        }
        __syncthreads();
        if (kt + 1 < ntiles) {
            uint32_t ua[8], ub[8];
            #pragma unroll
            for (int i = 0; i < 8; i++) {
                ua[i] = cvt_bf2(av[2*i+1], av[2*i]);
                ub[i] = cvt_bf2(bv[2*i+1], bv[2*i]);
            }
            asm volatile("st.shared.v4.b32 [%0], {%1,%2,%3,%4};"
                         :: "r"(stA0), "r"(ua[0]), "r"(ua[1]), "r"(ua[2]), "r"(ua[3]));
            asm volatile("st.shared.v4.b32 [%0], {%1,%2,%3,%4};"
                         :: "r"(stA1), "r"(ua[4]), "r"(ua[5]), "r"(ua[6]), "r"(ua[7]));
            asm volatile("st.shared.v4.b32 [%0], {%1,%2,%3,%4};"
                         :: "r"(stB0), "r"(ub[0]), "r"(ub[1]), "r"(ub[2]), "r"(ub[3]));
            asm volatile("st.shared.v4.b32 [%0], {%1,%2,%3,%4};"
                         :: "r"(stB1), "r"(ub[4]), "r"(ub[5]), "r"(ub[6]), "r"(ub[7]));
        }
        __syncthreads();
    }

    const int g2 = lane >> 2, q2 = lane & 3;
    const int chA = wid * 16 + g2;
    const int type = bm >> 8;
    const float esc = (type == 0) ? (QSCALE * LOG2E) : 1.0f;
    uint8_t* tbase = tiles + (size_t)(type * 8) * 32 * 8192 + (size_t)blockIdx.x * 8192;

    #pragma unroll
    for (int p0 = 0; p0 < 128; p0 += 32) {
        __syncthreads();
        #pragma unroll
        for (int t2 = 0; t2 < 4; t2++) {
            int nc  = (p0 >> 3) + t2;
            int pxl = nc * 8 + q2 * 2 - p0;
            sT[pxl][chA]         = acc[nc][0];
            sT[pxl + 1][chA]     = acc[nc][1];
            sT[pxl][chA + 8]     = acc[nc][2];
            sT[pxl + 1][chA + 8] = acc[nc][3];
        }
        __syncthreads();
        int pxl = t >> 3;
        int pixrow = p0 + pxl;
        #pragma unroll
        for (int s = 0; s < 2; s++) {
            int w = (t & 7) + s * 8;
            int hh = ((bm & 255) >> 5) + (w >> 2);
            int d0 = (w & 3) * 8;
            float4 f0 = *(float4*)&sT[pxl][w * 8];
            float4 f1 = *(float4*)&sT[pxl][w * 8 + 4];
            uint32_t b0 = cvt_bf2(f0.y * esc, f0.x * esc);
            uint32_t b1 = cvt_bf2(f0.w * esc, f0.z * esc);
            uint32_t b2 = cvt_bf2(f1.y * esc, f1.x * esc);
            uint32_t b3 = cvt_bf2(f1.w * esc, f1.z * esc);
            uint8_t* blob = tbase + (size_t)hh * 32 * 8192;
            *(uint4*)(blob + SW64R(pixrow * 64 + d0 * 2)) = make_uint4(b0, b1, b2, b3);
        }
    }
}

// ====== flash attention, split-K (unchanged, verified) ======================
__global__ __launch_bounds__(128, 4) void attn_kernel(
    const uint8_t* __restrict__ tiles, const uint32_t* __restrict__ posb,
    float* __restrict__ ypart, float* __restrict__ lpart)
{
    __shared__ __align__(128) char sQ[8192];
    __shared__ __align__(128) char sK[16384];
    __shared__ __align__(128) char sV[16384];
    __shared__ __align__(16)  char sPos[512];

    const int tid  = threadIdx.x;
    const int wid  = tid >> 5;
    const int lane = tid & 31;
    const int g    = lane >> 2;
    const int c    = lane & 3;
    const int h    = blockIdx.y;
    const int q0   = blockIdx.x * 128;
    const int z    = blockIdx.z;
    const int tb   = z * 16;

    const uint32_t qb = smem_u32(sQ), kb = smem_u32(sK), vb = smem_u32(sV);
    const uint32_t pbs = smem_u32(sPos);

    const uint8_t* tQ = tiles + (size_t)(h * 32 + blockIdx.x) * 8192;
    const uint8_t* tK = tiles + (size_t)((8 + h) * 32 + tb) * 8192;
    const uint8_t* tV = tiles + (size_t)((16 + h) * 32 + tb) * 8192;
    const uint8_t* tP = (const uint8_t*)(posb + h * 2048) + (size_t)tb * 256;

    {
        uint32_t o = tid << 4;
        #pragma unroll
        for (int s = 0; s < 4; s++) {
            CP16(qb + o + s * 2048, tQ + o + s * 2048);
            CP16(kb + o + s * 2048, tK + o + s * 2048);
            CP16(vb + o + s * 2048, tV + o + s * 2048);
        }
        if (tid < 16) CP16(pbs + (tid << 4), tP + (tid << 4));
        CPCOMMIT();
        CPWAIT0();
    }
    __syncthreads();

    uint32_t QAa0[4], QAa1[4], QAb0[4], QAb1[4];
    {
        int rowa = wid * 32 + (lane & 7) + ((lane >> 3) & 1) * 8;
        int ch   = lane >> 4;
        ldsm4(QAa0[0], QAa0[1], QAa0[2], QAa0[3], qb + SW64R(rowa * 64 + ch * 16));
        ldsm4(QAa1[0], QAa1[1], QAa1[2], QAa1[3], qb + SW64R(rowa * 64 + (2 + ch) * 16));
        int rowb = rowa + 16;
        ldsm4(QAb0[0], QAb0[1], QAb0[2], QAb0[3], qb + SW64R(rowb * 64 + ch * 16));
        ldsm4(QAb1[0], QAb1[1], QAb1[2], QAb1[3], qb + SW64R(rowb * 64 + (2 + ch) * 16));
    }
    uint32_t aK0, aK1, aV0, aV1;
    {
        int ko = (lane & 7) + (lane >> 4) * 8;
        int ch = (lane >> 3) & 1;
        aK0 = kb + SW64R(ko * 64 + ch * 16);
        aK1 = kb + SW64R(ko * 64 + (2 + ch) * 16);
    }
    {
        int ko = (lane & 7) + ((lane >> 3) & 1) * 8;
        int ch = lane >> 4;
        aV0 = vb + SW64R(ko * 64 + ch * 16);
        aV1 = vb + SW64R(ko * 64 + (2 + ch) * 16);
    }

    const uint32_t bOne = (lane < 4) ? 0x3F803F80u : 0u;
    float Ya[4][4], Yb[4][4], Ysa[4], Ysb[4];
    #pragma unroll
    for (int u = 0; u < 4; u++) {
        Ysa[u] = 0.f; Ysb[u] = 0.f;
        #pragma unroll
        for (int v = 0; v < 4; v++) { Ya[u][v] = 0.f; Yb[u][v] = 0.f; }
    }

    uint32_t kf[2][8];

    for (int it = 0; it < 16; it++) {
        const uint32_t bofs = (uint32_t)(it & 1) * 8192;

        if (it < 15) {
            const uint32_t nofs = (uint32_t)((it + 1) & 1) * 8192;
            const size_t jo = (size_t)(it + 1) * 8192;
            uint32_t o = tid << 4;
            #pragma unroll
            for (int s = 0; s < 4; s++) {
                CP16(kb + nofs + o + s * 2048, tK + jo + o + s * 2048);
                CP16(vb + nofs + o + s * 2048, tV + jo + o + s * 2048);
            }
            if (tid < 16)
                CP16(pbs + (((it + 1) & 1) << 8) + (tid << 4),
                     tP + (size_t)(it + 1) * 256 + (tid << 4));
            CPCOMMIT();
        }

        const uint32_t kA0 = aK0 + bofs, kA1 = aK1 + bofs;
        const uint32_t vA0 = aV0 + bofs, vA1 = aV1 + bofs;
        const uint32_t* sp = (const uint32_t*)(sPos + (it & 1) * 256);

        ldsm4(kf[0][0], kf[0][1], kf[0][2], kf[0][3], kA0);
        ldsm4(kf[0][4], kf[0][5], kf[0][6], kf[0][7], kA1);

        #pragma unroll
        for (int j = 0; j < 8; j++) {
            const uint32_t* kc = kf[j & 1];
            uint32_t* kn = kf[(j + 1) & 1];

            uint32_t pos0 = sp[j * 8 + c];
            uint32_t pos1 = sp[j * 8 + 4 + c];

            uint32_t v0, v1, v2, v3, w0, w1, w2, w3;
            ldsm4t(v0, v1, v2, v3, vA0 + j * 1024);
            ldsm4t(w0, w1, w2, w3, vA1 + j * 1024);
            if (j < 7) {
                ldsm4(kn[0], kn[1], kn[2], kn[3], kA0 + (j + 1) * 1024);
                ldsm4(kn[4], kn[5], kn[6], kn[7], kA1 + (j + 1) * 1024);
            }

            float Ca0[4] = {0.f,0.f,0.f,0.f}, Ca1[4] = {0.f,0.f,0.f,0.f};
            float Cb0[4] = {0.f,0.f,0.f,0.f}, Cb1[4] = {0.f,0.f,0.f,0.f};
            mma16816(Ca0, QAa0, kc[0], kc[1]);
            mma16816(Ca0, QAa1, kc[4], kc[5]);
            mma16816(Ca1, QAa0, kc[2], kc[3]);
            mma16816(Ca1, QAa1, kc[6], kc[7]);
            mma16816(Cb0, QAb0, kc[0], kc[1]);
            mma16816(Cb0, QAb1, kc[4], kc[5]);
            mma16816(Cb1, QAb0, kc[2], kc[3]);
            mma16816(Cb1, QAb1, kc[6], kc[7]);

            uint32_t Pa[4], Pb[4];
            Pa[0] = pexp2(cvt_bf2(Ca0[1], Ca0[0]), pos0);
            Pa[1] = pexp2(cvt_bf2(Ca0[3], Ca0[2]), pos0);
            Pa[2] = pexp2(cvt_bf2(Ca1[1], Ca1[0]), pos1);
            Pa[3] = pexp2(cvt_bf2(Ca1[3], Ca1[2]), pos1);
            Pb[0] = pexp2(cvt_bf2(Cb0[1], Cb0[0]), pos0);
            Pb[1] = pexp2(cvt_bf2(Cb0[3], Cb0[2]), pos0);
            Pb[2] = pexp2(cvt_bf2(Cb1[1], Cb1[0]), pos1);
            Pb[3] = pexp2(cvt_bf2(Cb1[3], Cb1[2]), pos1);

            mma16816(Ya[0], Pa, v0, v1);
            mma16816(Ya[1], Pa, v2, v3);
            mma16816(Ya[2], Pa, w0, w1);
            mma16816(Ya[3], Pa, w2, w3);
            mma16816(Ysa,   Pa, bOne, bOne);
            mma16816(Yb[0], Pb, v0, v1);
            mma16816(Yb[1], Pb, v2, v3);
            mma16816(Yb[2], Pb, w0, w1);
            mma16816(Yb[3], Pb, w2, w3);
            mma16816(Ysb,   Pb, bOne, bOne);
        }

        if (it < 15) CPWAIT0();
        __syncthreads();
    }

    float* yp = ypart + (size_t)z * 256 * HW;
    float* lp = lpart + (size_t)z * 8 * HW;
    int rowa = q0 + wid * 32 + g;
    int rowb = rowa + 16;
    #pragma unroll
    for (int v = 0; v < 4; v++) {
        int d = h * 32 + v * 8 + 2 * c;
        yp[(size_t)d * HW + rowa]           = Ya[v][0];
        yp[(size_t)(d + 1) * HW + rowa]     = Ya[v][1];
        yp[(size_t)d * HW + rowa + 8]       = Ya[v][2];
        yp[(size_t)(d + 1) * HW + rowa + 8] = Ya[v][3];
        yp[(size_t)d * HW + rowb]           = Yb[v][0];
        yp[(size_t)(d + 1) * HW + rowb]     = Yb[v][1];
        yp[(size_t)d * HW + rowb + 8]       = Yb[v][2];
        yp[(size_t)(d + 1) * HW + rowb + 8] = Yb[v][3];
    }
    if (c == 0) {
        lp[(size_t)h * HW + rowa]      = Ysa[0];
        lp[(size_t)h * HW + rowa + 8]  = Ysa[2];
        lp[(size_t)h * HW + rowb]      = Ysb[0];
        lp[(size_t)h * HW + rowb + 8]  = Ysb[2];
    }
}

// ------ combine partials -> normalized bf16 swizzled y tiles ----------------
// grid = 256 blobs (h*32 + jb), 128 threads = one pixel row each.
__global__ __launch_bounds__(128) void combine_tiles_kernel(
    const float* __restrict__ ypart, const float* __restrict__ lpart,
    uint8_t* __restrict__ ytiles)
{
    const int blob = blockIdx.x;
    const int h = blob >> 5, jb = blob & 31;
    const int pix = threadIdx.x;
    const int n = jb * 128 + pix;
    float inv = 1.f / (lpart[(size_t)h * HW + n] +
                       lpart[8 * HW + (size_t)h * HW + n]);
    const float* y0 = ypart + (size_t)(h * 32) * HW + n;
    const float* y1 = y0 + 256 * HW;
    uint32_t b[16];
    #pragma unroll
    for (int i = 0; i < 16; i++) {
        float lo = (y0[(size_t)(2*i) * HW]     + y1[(size_t)(2*i) * HW])     * inv;
        float hi = (y0[(size_t)(2*i+1) * HW]   + y1[(size_t)(2*i+1) * HW])   * inv;
        b[i] = cvt_bf2(hi, lo);
    }
    uint8_t* bp = ytiles + (size_t)blob * 8192;
    *(uint4*)(bp + SW64R(pix * 64))      = make_uint4(b[0],  b[1],  b[2],  b[3]);
    *(uint4*)(bp + SW64R(pix * 64 + 16)) = make_uint4(b[4],  b[5],  b[6],  b[7]);
    *(uint4*)(bp + SW64R(pix * 64 + 32)) = make_uint4(b[8],  b[9],  b[10], b[11]);
    *(uint4*)(bp + SW64R(pix * 64 + 48)) = make_uint4(b[12], b[13], b[14], b[15]);
}

// ===== proj GEMM: B from pre-packed y tiles via cp.async ====================
// grid (32, 4): bn = blockIdx.x*128 pixels, bm = blockIdx.y*128 channels.
// k-tile kt = head kt (32 channels); B tile = blob (kt*32 + blockIdx.x).
__global__ __launch_bounds__(256) void proj_gemm_kernel(
    const float* __restrict__ A, const uint8_t* __restrict__ ytiles,
    const float* __restrict__ bias, float* __restrict__ C)
{
    __shared__ __align__(128) char sA[8192];
    __shared__ __align__(128) char sB[16384];   // double buffer
    const int t = threadIdx.x, wid = t >> 5, lane = t & 31;
    const int bm = blockIdx.y * 128, bn = blockIdx.x * 128;
    const int K = 256, N = HW;
    const uint32_t ab = smem_u32(sA), bb = smem_u32(sB);

    const int ma = t >> 1, qa = t & 1;

    const int fr = wid * 16 + (lane & 7) + ((lane >> 3) & 1) * 8;
    const uint32_t aA0 = ab + SW64R(fr * 64 + (lane >> 4) * 16);
    const uint32_t aA1 = ab + SW64R(fr * 64 + (2 + (lane >> 4)) * 16);
    const int br = (lane & 7) + (lane >> 4) * 8;
    const uint32_t aB0 = bb + SW64R(br * 64 + ((lane >> 3) & 1) * 16);
    const uint32_t aB1 = bb + SW64R(br * 64 + (2 + ((lane >> 3) & 1)) * 16);

    const uint32_t stA0 = ab + SW64R(ma * 64 + qa * 32);
    const uint32_t stA1 = ab + SW64R(ma * 64 + qa * 32 + 16);

    const uint8_t* ybase = ytiles + (size_t)blockIdx.x * 8192;

    float acc[16][4];
    #pragma unroll
    for (int i = 0; i < 16; i++)
        #pragma unroll
        for (int v = 0; v < 4; v++) acc[i][v] = 0.f;

    float av[16];

    // prologue: A0 staged, B0 cp.async
    {
        const float* ap = A + (size_t)(bm + ma) * K + qa * 16;
        #pragma unroll
        for (int i = 0; i < 4; i++) {
            float4 x = ((const float4*)ap)[i];
            av[4*i] = x.x; av[4*i+1] = x.y; av[4*i+2] = x.z; av[4*i+3] = x.w;
        }
        uint32_t ua[8];
        #pragma unroll
        for (int i = 0; i < 8; i++) ua[i] = cvt_bf2(av[2*i+1], av[2*i]);
        asm volatile("st.shared.v4.b32 [%0], {%1,%2,%3,%4};"
                     :: "r"(stA0), "r"(ua[0]), "r"(ua[1]), "r"(ua[2]), "r"(ua[3]));
        asm volatile("st.shared.v4.b32 [%0], {%1,%2,%3,%4};"
                     :: "r"(stA1), "r"(ua[4]), "r"(ua[5]), "r"(ua[6]), "r"(ua[7]));
        uint32_t o = t << 4;
        CP16(bb + o,        ybase + o);
        CP16(bb + o + 4096, ybase + o + 4096);
        CPCOMMIT();
        CPWAIT0();
    }
    __syncthreads();

    for (int kt = 0; kt < 8; kt++) {
        // prefetch: next A into regs, next B via cp.async
        if (kt < 7) {
            const float* ap = A + (size_t)(bm + ma) * K + (kt + 1) * 32 + qa * 16;
            #pragma unroll
            for (int i = 0; i < 4; i++) {
                float4 x = ((const float4*)ap)[i];
                av[4*i] = x.x; av[4*i+1] = x.y; av[4*i+2] = x.z; av[4*i+3] = x.w;
            }
            const uint8_t* yb2 = ybase + (size_t)(kt + 1) * 32 * 8192;
            uint32_t nofs = (uint32_t)((kt + 1) & 1) * 8192;
            uint32_t o = t << 4;
            CP16(bb + nofs + o,        yb2 + o);
            CP16(bb + nofs + o + 4096, yb2 + o + 4096);
            CPCOMMIT();
        }

        const uint32_t bofs = (uint32_t)(kt & 1) * 8192;
        uint32_t A0[4], A1[4];
        ldsm4(A0[0], A0[1], A0[2], A0[3], aA0);
        ldsm4(A1[0], A1[1], A1[2], A1[3], aA1);
        #pragma unroll
        for (int nch = 0; nch < 8; nch++) {
            uint32_t b00, b01, b02, b03, b10, b11, b12, b13;
            ldsm4(b00, b01, b02, b03, aB0 + bofs + nch * 1024);
            ldsm4(b10, b11, b12, b13, aB1 + bofs + nch * 1024);
            mma16816(acc[2*nch],   A0, b00, b01);
            mma16816(acc[2*nch],   A1, b10, b11);
            mma16816(acc[2*nch+1], A0, b02, b03);
            mma16816(acc[2*nch+1], A1, b12, b13);
        }
        __syncthreads();
        if (kt < 7) {
            uint32_t ua[8];
            #pragma unroll
            for (int i = 0; i < 8; i++) ua[i] = cvt_bf2(av[2*i+1], av[2*i]);
            asm volatile("st.shared.v4.b32 [%0], {%1,%2,%3,%4};"
                         :: "r"(stA0), "r"(ua[0]), "r"(ua[1]), "r"(ua[2]), "r"(ua[3]));
            asm volatile("st.shared.v4.b32 [%0], {%1,%2,%3,%4};"
                         :: "r"(stA1), "r"(ua[4]), "r"(ua[5]), "r"(ua[6]), "r"(ua[7]));
            CPWAIT0();
        }
        __syncthreads();
    }

    int r0 = bm + wid * 16 + (lane >> 2);
    float bv0 = bias[r0];
    float bv1 = bias[r0 + 8];
    float* c0p = C + (size_t)r0 * N + bn + (lane & 3) * 2;
    float* c1p = C + (size_t)(r0 + 8) * N + bn + (lane & 3) * 2;
    #pragma unroll
    for (int nc = 0; nc < 16; nc++) {
        *(float2*)(c0p + nc * 8) = make_float2(acc[nc][0] + bv0, acc[nc][1] + bv0);
        *(float2*)(c1p + nc * 8) = make_float2(acc[nc][2] + bv1, acc[nc][3] + bv1);
    }
}

// --------------- residual + channel LayerNorm (z cached in regs) ------------
__global__ __launch_bounds__(256) void ln_kernel(
    const float* __restrict__ x, const float* __restrict__ yp,
    const float* __restrict__ gamma, const float* __restrict__ beta,
    float* __restrict__ out)
{
    __shared__ float ssum[8][32], ssq[8][32];
    int nx = threadIdx.x & 31;
    int cg = threadIdx.x >> 5;
    int n  = blockIdx.x * 32 + nx;

    float z[64];
    float sum = 0.f, sq = 0.f;
    #pragma unroll
    for (int i = 0; i < 64; i++) {
        int c = cg + i * 8;
        z[i] = x[(size_t)c * HW + n] + yp[(size_t)c * HW + n];
        sum += z[i]; sq += z[i] * z[i];
    }
    ssum[cg][nx] = sum; ssq[cg][nx] = sq;
    __syncthreads();
    float tot = 0.f, totsq = 0.f;
    #pragma unroll
    for (int g = 0; g < 8; g++) { tot += ssum[g][nx]; totsq += ssq[g][nx]; }
    float mu   = tot * (1.f / 512.f);
    float var  = totsq * (1.f / 512.f) - mu * mu;
    float rstd = rsqrtf(var + 1e-5f);
    #pragma unroll
    for (int i = 0; i < 64; i++) {
        int c = cg + i * 8;
        out[(size_t)c * HW + n] = (z[i] - mu) * rstd * gamma[c] + beta[c];
    }
}

// -----------------------------------------------------------------------------
extern "C" void kernel_launch(void* const* d_in, const int* in_sizes, int n_in,
                              void* d_out, int out_size) {
    const float* x        = (const float*)d_in[0];
    const float* w_qkv    = (const float*)d_in[1];
    const float* w_proj   = (const float*)d_in[2];
    const float* b_proj   = (const float*)d_in[3];
    const float* pos_bias = (const float*)d_in[4];
    const float* gamma    = (const float*)d_in[5];
    const float* beta     = (const float*)d_in[6];
    float* out = (float*)d_out;

    float *proj, *ypart, *lpart;
    uint8_t *tiles, *ytiles;
    uint32_t* posb;
    cudaGetSymbolAddress((void**)&proj,   g_proj);
    cudaGetSymbolAddress((void**)&ypart,  g_ypart);
    cudaGetSymbolAddress((void**)&lpart,  g_lpart);
    cudaGetSymbolAddress((void**)&tiles,  g_tiles);
    cudaGetSymbolAddress((void**)&ytiles, g_ytiles);
    cudaGetSymbolAddress((void**)&posb,   g_posb);

    pos_kernel<<<64, 256>>>(pos_bias, posb);
    qkv_gemm_kernel<<<dim3(32, 6), 256>>>(w_qkv, x, tiles, 512);
    attn_kernel<<<dim3(32, 8, 2), 128>>>(tiles, posb, ypart, lpart);
    combine_tiles_kernel<<<256, 128>>>(ypart, lpart, ytiles);
    proj_gemm_kernel<<<dim3(32, 4), 256>>>(w_proj, ytiles, b_proj, proj);
    ln_kernel<<<128, 256>>>(x, proj, gamma, beta, out);
}

// round 15
// speedup vs baseline: 1.0707x; 1.0155x over previous
#include <cuda_runtime.h>
#include <cuda_bf16.h>
#include <math.h>
#include <stdint.h>

// ---------------------------------------------------------------------------
// FixFeatureAttention sm_103.  R15 = R14 with combine_tiles parallelized 4x
// (grid (256,4): each CTA does a quarter-blob; 131k threads vs 32k).
// ---------------------------------------------------------------------------

#define HW 4096
#define LOG2E 1.4426950408889634f
#define QSCALE 0.17677669529663687f   // 1/sqrt(32)

__device__ float    g_ypart[2 * 256 * HW];
__device__ float    g_lpart[2 * 8 * HW];
__device__ float    g_proj[512 * HW];
__device__ uint8_t  g_tiles[6 * 1024 * 1024];   // q/k/v bf16 swizzled tiles
__device__ uint8_t  g_ytiles[2 * 1024 * 1024];  // normalized y bf16 tiles
__device__ uint32_t g_posb[8 * 2048];

#define SW64R(o) ((o) ^ ((((o) >> 7) & 3) << 4))

__device__ __forceinline__ uint32_t smem_u32(const void* p) {
    uint32_t a;
    asm("{.reg .u64 t; cvta.to.shared.u64 t, %1; cvt.u32.u64 %0, t;}" : "=r"(a) : "l"(p));
    return a;
}
__device__ __forceinline__ uint32_t cvt_bf2(float hi, float lo) {
    uint32_t r;
    asm("cvt.rn.bf16x2.f32 %0, %1, %2;" : "=r"(r) : "f"(hi), "f"(lo));
    return r;
}
__device__ __forceinline__ void ldsm4(uint32_t& r0, uint32_t& r1, uint32_t& r2,
                                      uint32_t& r3, uint32_t a) {
    asm volatile("ldmatrix.sync.aligned.m8n8.x4.shared.b16 {%0,%1,%2,%3}, [%4];"
                 : "=r"(r0), "=r"(r1), "=r"(r2), "=r"(r3) : "r"(a));
}
__device__ __forceinline__ void ldsm4t(uint32_t& r0, uint32_t& r1, uint32_t& r2,
                                       uint32_t& r3, uint32_t a) {
    asm volatile("ldmatrix.sync.aligned.m8n8.x4.trans.shared.b16 {%0,%1,%2,%3}, [%4];"
                 : "=r"(r0), "=r"(r1), "=r"(r2), "=r"(r3) : "r"(a));
}
__device__ __forceinline__ void mma16816(float* c, const uint32_t* a,
                                         uint32_t b0, uint32_t b1) {
    asm("mma.sync.aligned.m16n8k16.row.col.f32.bf16.bf16.f32 "
        "{%0,%1,%2,%3},{%4,%5,%6,%7},{%8,%9},{%0,%1,%2,%3};"
        : "+f"(c[0]), "+f"(c[1]), "+f"(c[2]), "+f"(c[3])
        : "r"(a[0]), "r"(a[1]), "r"(a[2]), "r"(a[3]), "r"(b0), "r"(b1));
}
#define CP16(dst, src) asm volatile("cp.async.cg.shared.global [%0], [%1], 16;" \
                                    :: "r"(dst), "l"(src) : "memory")
#define CPCOMMIT()     asm volatile("cp.async.commit_group;" ::: "memory")
#define CPWAIT0()      asm volatile("cp.async.wait_group 0;" ::: "memory")

__device__ __forceinline__ uint32_t pexp2(uint32_t xu, uint32_t posu) {
    uint32_t x, t, u, f, p, q;
    asm("add.rn.bf16x2 %0, %1, %2;" : "=r"(x) : "r"(xu), "r"(posu));
    asm("add.rn.bf16x2 %0, %1, %2;" : "=r"(t) : "r"(x), "r"(0x43404340u));
    asm("sub.rn.bf16x2 %0, %1, %2;" : "=r"(u) : "r"(t), "r"(0x43404340u));
    asm("sub.rn.bf16x2 %0, %1, %2;" : "=r"(f) : "r"(x), "r"(u));
    asm("fma.rn.bf16x2 %0, %1, %2, %3;" : "=r"(p)
        : "r"(0x3E783E78u), "r"(f), "r"(0x3F343F34u));
    asm("fma.rn.bf16x2 %0, %1, %2, %3;" : "=r"(q)
        : "r"(p), "r"(f), "r"(0x3F803F80u));
    return (t & 0x007F007Fu) * 128u + q + 0xDFFFE000u;
}

// ----------------- pos bias bilinear 16->64, packed bf16x2 (xLOG2E) ---------
__global__ void pos_kernel(const float* __restrict__ pb, uint32_t* __restrict__ posb) {
    int i = blockIdx.x * 256 + threadIdx.x;
    if (i >= 8 * 2048) return;
    int h = i >> 11, jp = i & 2047;
    float v[2];
    #pragma unroll
    for (int s = 0; s < 2; s++) {
        int j = jp * 2 + s;
        int py = j >> 6, px = j & 63;
        float sy = (py + 0.5f) * 0.25f - 0.5f;
        float sx = (px + 0.5f) * 0.25f - 0.5f;
        float fy0 = floorf(sy), fx0 = floorf(sx);
        float wy = sy - fy0, wx = sx - fx0;
        int y0 = max((int)fy0, 0), y1 = min((int)fy0 + 1, 15);
        int x0 = max((int)fx0, 0), x1 = min((int)fx0 + 1, 15);
        const float* p = pb + h * 256;
        float v00 = p[y0 * 16 + x0], v01 = p[y0 * 16 + x1];
        float v10 = p[y1 * 16 + x0], v11 = p[y1 * 16 + x1];
        float va = v00 + (v01 - v00) * wx;
        float vb = v10 + (v11 - v10) * wx;
        v[s] = (va + (vb - va) * wy) * LOG2E;
    }
    posb[i] = cvt_bf2(v[1], v[0]);
}

// ============ qkv GEMM: C = w_qkv * x, fused bf16 tile pack =================
__global__ __launch_bounds__(256) void qkv_gemm_kernel(
    const float* __restrict__ A, const float* __restrict__ B,
    uint8_t* __restrict__ tiles, int K)
{
    __shared__ __align__(128) char sA[8192];
    __shared__ __align__(128) char sB[8192];
    __shared__ __align__(16)  float sT[32][132];
    const int t = threadIdx.x, wid = t >> 5, lane = t & 31;
    const int bm = blockIdx.y * 128, bn = blockIdx.x * 128;
    const uint32_t ab = smem_u32(sA), bb = smem_u32(sB);

    const int ma = t >> 1, qa = t & 1;
    const int nb = t & 127, kh = t >> 7;

    const int fr = wid * 16 + (lane & 7) + ((lane >> 3) & 1) * 8;
    const uint32_t aA0 = ab + SW64R(fr * 64 + (lane >> 4) * 16);
    const uint32_t aA1 = ab + SW64R(fr * 64 + (2 + (lane >> 4)) * 16);
    const int br = (lane & 7) + (lane >> 4) * 8;
    const uint32_t aB0 = bb + SW64R(br * 64 + ((lane >> 3) & 1) * 16);
    const uint32_t aB1 = bb + SW64R(br * 64 + (2 + ((lane >> 3) & 1)) * 16);

    const uint32_t stA0 = ab + SW64R(ma * 64 + qa * 32);
    const uint32_t stA1 = ab + SW64R(ma * 64 + qa * 32 + 16);
    const uint32_t stB0 = bb + SW64R(nb * 64 + kh * 32);
    const uint32_t stB1 = bb + SW64R(nb * 64 + kh * 32 + 16);

    float acc[16][4];
    #pragma unroll
    for (int i = 0; i < 16; i++)
        #pragma unroll
        for (int v = 0; v < 4; v++) acc[i][v] = 0.f;

    const int ntiles = K >> 5;
    float av[16], bv[16];

    {
        const float* ap = A + (size_t)(bm + ma) * K + qa * 16;
        #pragma unroll
        for (int i = 0; i < 4; i++) {
            float4 x = ((const float4*)ap)[i];
            av[4*i] = x.x; av[4*i+1] = x.y; av[4*i+2] = x.z; av[4*i+3] = x.w;
        }
        const float* bp = B + (size_t)(kh * 16) * HW + bn + nb;
        #pragma unroll
        for (int i = 0; i < 16; i++) bv[i] = bp[(size_t)i * HW];
        uint32_t ua[8], ub[8];
        #pragma unroll
        for (int i = 0; i < 8; i++) {
            ua[i] = cvt_bf2(av[2*i+1], av[2*i]);
            ub[i] = cvt_bf2(bv[2*i+1], bv[2*i]);
        }
        asm volatile("st.shared.v4.b32 [%0], {%1,%2,%3,%4};"
                     :: "r"(stA0), "r"(ua[0]), "r"(ua[1]), "r"(ua[2]), "r"(ua[3]));
        asm volatile("st.shared.v4.b32 [%0], {%1,%2,%3,%4};"
                     :: "r"(stA1), "r"(ua[4]), "r"(ua[5]), "r"(ua[6]), "r"(ua[7]));
        asm volatile("st.shared.v4.b32 [%0], {%1,%2,%3,%4};"
                     :: "r"(stB0), "r"(ub[0]), "r"(ub[1]), "r"(ub[2]), "r"(ub[3]));
        asm volatile("st.shared.v4.b32 [%0], {%1,%2,%3,%4};"
                     :: "r"(stB1), "r"(ub[4]), "r"(ub[5]), "r"(ub[6]), "r"(ub[7]));
    }
    __syncthreads();

    for (int kt = 0; kt < ntiles; kt++) {
        if (kt + 1 < ntiles) {
            int k0 = (kt + 1) * 32;
            const float* ap = A + (size_t)(bm + ma) * K + k0 + qa * 16;
            #pragma unroll
            for (int i = 0; i < 4; i++) {
                float4 x = ((const float4*)ap)[i];
                av[4*i] = x.x; av[4*i+1] = x.y; av[4*i+2] = x.z; av[4*i+3] = x.w;
            }
            const float* bp = B + (size_t)(k0 + kh * 16) * HW + bn + nb;
            #pragma unroll
            for (int i = 0; i < 16; i++) bv[i] = bp[(size_t)i * HW];
        }

        uint32_t A0[4], A1[4];
        ldsm4(A0[0], A0[1], A0[2], A0[3], aA0);
        ldsm4(A1[0], A1[1], A1[2], A1[3], aA1);
        #pragma unroll
        for (int nch = 0; nch < 8; nch++) {
            uint32_t b00, b01, b02, b03, b10, b11, b12, b13;
            ldsm4(b00, b01, b02, b03, aB0 + nch * 1024);
            ldsm4(b10, b11, b12, b13, aB1 + nch * 1024);
            mma16816(acc[2*nch],   A0, b00, b01);
            mma16816(acc[2*nch],   A1, b10, b11);
            mma16816(acc[2*nch+1], A0, b02, b03);
            mma16816(acc[2*nch+1], A1, b12, b13);
        }
        __syncthreads();
        if (kt + 1 < ntiles) {
            uint32_t ua[8], ub[8];
            #pragma unroll
            for (int i = 0; i < 8; i++) {
                ua[i] = cvt_bf2(av[2*i+1], av[2*i]);
                ub[i] = cvt_bf2(bv[2*i+1], bv[2*i]);
            }
            asm volatile("st.shared.v4.b32 [%0], {%1,%2,%3,%4};"
                         :: "r"(stA0), "r"(ua[0]), "r"(ua[1]), "r"(ua[2]), "r"(ua[3]));
            asm volatile("st.shared.v4.b32 [%0], {%1,%2,%3,%4};"
                         :: "r"(stA1), "r"(ua[4]), "r"(ua[5]), "r"(ua[6]), "r"(ua[7]));
            asm volatile("st.shared.v4.b32 [%0], {%1,%2,%3,%4};"
                         :: "r"(stB0), "r"(ub[0]), "r"(ub[1]), "r"(ub[2]), "r"(ub[3]));
            asm volatile("st.shared.v4.b32 [%0], {%1,%2,%3,%4};"
                         :: "r"(stB1), "r"(ub[4]), "r"(ub[5]), "r"(ub[6]), "r"(ub[7]));
        }
        __syncthreads();
    }

    const int g2 = lane >> 2, q2 = lane & 3;
    const int chA = wid * 16 + g2;
    const int type = bm >> 8;
    const float esc = (type == 0) ? (QSCALE * LOG2E) : 1.0f;
    uint8_t* tbase = tiles + (size_t)(type * 8) * 32 * 8192 + (size_t)blockIdx.x * 8192;

    #pragma unroll
    for (int p0 = 0; p0 < 128; p0 += 32) {
        __syncthreads();
        #pragma unroll
        for (int t2 = 0; t2 < 4; t2++) {
            int nc  = (p0 >> 3) + t2;
            int pxl = nc * 8 + q2 * 2 - p0;
            sT[pxl][chA]         = acc[nc][0];
            sT[pxl + 1][chA]     = acc[nc][1];
            sT[pxl][chA + 8]     = acc[nc][2];
            sT[pxl + 1][chA + 8] = acc[nc][3];
        }
        __syncthreads();
        int pxl = t >> 3;
        int pixrow = p0 + pxl;
        #pragma unroll
        for (int s = 0; s < 2; s++) {
            int w = (t & 7) + s * 8;
            int hh = ((bm & 255) >> 5) + (w >> 2);
            int d0 = (w & 3) * 8;
            float4 f0 = *(float4*)&sT[pxl][w * 8];
            float4 f1 = *(float4*)&sT[pxl][w * 8 + 4];
            uint32_t b0 = cvt_bf2(f0.y * esc, f0.x * esc);
            uint32_t b1 = cvt_bf2(f0.w * esc, f0.z * esc);
            uint32_t b2 = cvt_bf2(f1.y * esc, f1.x * esc);
            uint32_t b3 = cvt_bf2(f1.w * esc, f1.z * esc);
            uint8_t* blob = tbase + (size_t)hh * 32 * 8192;
            *(uint4*)(blob + SW64R(pixrow * 64 + d0 * 2)) = make_uint4(b0, b1, b2, b3);
        }
    }
}

// ====== flash attention, split-K (unchanged, verified) ======================
__global__ __launch_bounds__(128, 4) void attn_kernel(
    const uint8_t* __restrict__ tiles, const uint32_t* __restrict__ posb,
    float* __restrict__ ypart, float* __restrict__ lpart)
{
    __shared__ __align__(128) char sQ[8192];
    __shared__ __align__(128) char sK[16384];
    __shared__ __align__(128) char sV[16384];
    __shared__ __align__(16)  char sPos[512];

    const int tid  = threadIdx.x;
    const int wid  = tid >> 5;
    const int lane = tid & 31;
    const int g    = lane >> 2;
    const int c    = lane & 3;
    const int h    = blockIdx.y;
    const int q0   = blockIdx.x * 128;
    const int z    = blockIdx.z;
    const int tb   = z * 16;

    const uint32_t qb = smem_u32(sQ), kb = smem_u32(sK), vb = smem_u32(sV);
    const uint32_t pbs = smem_u32(sPos);

    const uint8_t* tQ = tiles + (size_t)(h * 32 + blockIdx.x) * 8192;
    const uint8_t* tK = tiles + (size_t)((8 + h) * 32 + tb) * 8192;
    const uint8_t* tV = tiles + (size_t)((16 + h) * 32 + tb) * 8192;
    const uint8_t* tP = (const uint8_t*)(posb + h * 2048) + (size_t)tb * 256;

    {
        uint32_t o = tid << 4;
        #pragma unroll
        for (int s = 0; s < 4; s++) {
            CP16(qb + o + s * 2048, tQ + o + s * 2048);
            CP16(kb + o + s * 2048, tK + o + s * 2048);
            CP16(vb + o + s * 2048, tV + o + s * 2048);
        }
        if (tid < 16) CP16(pbs + (tid << 4), tP + (tid << 4));
        CPCOMMIT();
        CPWAIT0();
    }
    __syncthreads();

    uint32_t QAa0[4], QAa1[4], QAb0[4], QAb1[4];
    {
        int rowa = wid * 32 + (lane & 7) + ((lane >> 3) & 1) * 8;
        int ch   = lane >> 4;
        ldsm4(QAa0[0], QAa0[1], QAa0[2], QAa0[3], qb + SW64R(rowa * 64 + ch * 16));
        ldsm4(QAa1[0], QAa1[1], QAa1[2], QAa1[3], qb + SW64R(rowa * 64 + (2 + ch) * 16));
        int rowb = rowa + 16;
        ldsm4(QAb0[0], QAb0[1], QAb0[2], QAb0[3], qb + SW64R(rowb * 64 + ch * 16));
        ldsm4(QAb1[0], QAb1[1], QAb1[2], QAb1[3], qb + SW64R(rowb * 64 + (2 + ch) * 16));
    }
    uint32_t aK0, aK1, aV0, aV1;
    {
        int ko = (lane & 7) + (lane >> 4) * 8;
        int ch = (lane >> 3) & 1;
        aK0 = kb + SW64R(ko * 64 + ch * 16);
        aK1 = kb + SW64R(ko * 64 + (2 + ch) * 16);
    }
    {
        int ko = (lane & 7) + ((lane >> 3) & 1) * 8;
        int ch = lane >> 4;
        aV0 = vb + SW64R(ko * 64 + ch * 16);
        aV1 = vb + SW64R(ko * 64 + (2 + ch) * 16);
    }

    const uint32_t bOne = (lane < 4) ? 0x3F803F80u : 0u;
    float Ya[4][4], Yb[4][4], Ysa[4], Ysb[4];
    #pragma unroll
    for (int u = 0; u < 4; u++) {
        Ysa[u] = 0.f; Ysb[u] = 0.f;
        #pragma unroll
        for (int v = 0; v < 4; v++) { Ya[u][v] = 0.f; Yb[u][v] = 0.f; }
    }

    uint32_t kf[2][8];

    for (int it = 0; it < 16; it++) {
        const uint32_t bofs = (uint32_t)(it & 1) * 8192;

        if (it < 15) {
            const uint32_t nofs = (uint32_t)((it + 1) & 1) * 8192;
            const size_t jo = (size_t)(it + 1) * 8192;
            uint32_t o = tid << 4;
            #pragma unroll
            for (int s = 0; s < 4; s++) {
                CP16(kb + nofs + o + s * 2048, tK + jo + o + s * 2048);
                CP16(vb + nofs + o + s * 2048, tV + jo + o + s * 2048);
            }
            if (tid < 16)
                CP16(pbs + (((it + 1) & 1) << 8) + (tid << 4),
                     tP + (size_t)(it + 1) * 256 + (tid << 4));
            CPCOMMIT();
        }

        const uint32_t kA0 = aK0 + bofs, kA1 = aK1 + bofs;
        const uint32_t vA0 = aV0 + bofs, vA1 = aV1 + bofs;
        const uint32_t* sp = (const uint32_t*)(sPos + (it & 1) * 256);

        ldsm4(kf[0][0], kf[0][1], kf[0][2], kf[0][3], kA0);
        ldsm4(kf[0][4], kf[0][5], kf[0][6], kf[0][7], kA1);

        #pragma unroll
        for (int j = 0; j < 8; j++) {
            const uint32_t* kc = kf[j & 1];
            uint32_t* kn = kf[(j + 1) & 1];

            uint32_t pos0 = sp[j * 8 + c];
            uint32_t pos1 = sp[j * 8 + 4 + c];

            uint32_t v0, v1, v2, v3, w0, w1, w2, w3;
            ldsm4t(v0, v1, v2, v3, vA0 + j * 1024);
            ldsm4t(w0, w1, w2, w3, vA1 + j * 1024);
            if (j < 7) {
                ldsm4(kn[0], kn[1], kn[2], kn[3], kA0 + (j + 1) * 1024);
                ldsm4(kn[4], kn[5], kn[6], kn[7], kA1 + (j + 1) * 1024);
            }

            float Ca0[4] = {0.f,0.f,0.f,0.f}, Ca1[4] = {0.f,0.f,0.f,0.f};
            float Cb0[4] = {0.f,0.f,0.f,0.f}, Cb1[4] = {0.f,0.f,0.f,0.f};
            mma16816(Ca0, QAa0, kc[0], kc[1]);
            mma16816(Ca0, QAa1, kc[4], kc[5]);
            mma16816(Ca1, QAa0, kc[2], kc[3]);
            mma16816(Ca1, QAa1, kc[6], kc[7]);
            mma16816(Cb0, QAb0, kc[0], kc[1]);
            mma16816(Cb0, QAb1, kc[4], kc[5]);
            mma16816(Cb1, QAb0, kc[2], kc[3]);
            mma16816(Cb1, QAb1, kc[6], kc[7]);

            uint32_t Pa[4], Pb[4];
            Pa[0] = pexp2(cvt_bf2(Ca0[1], Ca0[0]), pos0);
            Pa[1] = pexp2(cvt_bf2(Ca0[3], Ca0[2]), pos0);
            Pa[2] = pexp2(cvt_bf2(Ca1[1], Ca1[0]), pos1);
            Pa[3] = pexp2(cvt_bf2(Ca1[3], Ca1[2]), pos1);
            Pb[0] = pexp2(cvt_bf2(Cb0[1], Cb0[0]), pos0);
            Pb[1] = pexp2(cvt_bf2(Cb0[3], Cb0[2]), pos0);
            Pb[2] = pexp2(cvt_bf2(Cb1[1], Cb1[0]), pos1);
            Pb[3] = pexp2(cvt_bf2(Cb1[3], Cb1[2]), pos1);

            mma16816(Ya[0], Pa, v0, v1);
            mma16816(Ya[1], Pa, v2, v3);
            mma16816(Ya[2], Pa, w0, w1);
            mma16816(Ya[3], Pa, w2, w3);
            mma16816(Ysa,   Pa, bOne, bOne);
            mma16816(Yb[0], Pb, v0, v1);
            mma16816(Yb[1], Pb, v2, v3);
            mma16816(Yb[2], Pb, w0, w1);
            mma16816(Yb[3], Pb, w2, w3);
            mma16816(Ysb,   Pb, bOne, bOne);
        }

        if (it < 15) CPWAIT0();
        __syncthreads();
    }

    float* yp = ypart + (size_t)z * 256 * HW;
    float* lp = lpart + (size_t)z * 8 * HW;
    int rowa = q0 + wid * 32 + g;
    int rowb = rowa + 16;
    #pragma unroll
    for (int v = 0; v < 4; v++) {
        int d = h * 32 + v * 8 + 2 * c;
        yp[(size_t)d * HW + rowa]           = Ya[v][0];
        yp[(size_t)(d + 1) * HW + rowa]     = Ya[v][1];
        yp[(size_t)d * HW + rowa + 8]       = Ya[v][2];
        yp[(size_t)(d + 1) * HW + rowa + 8] = Ya[v][3];
        yp[(size_t)d * HW + rowb]           = Yb[v][0];
        yp[(size_t)(d + 1) * HW + rowb]     = Yb[v][1];
        yp[(size_t)d * HW + rowb + 8]       = Yb[v][2];
        yp[(size_t)(d + 1) * HW + rowb + 8] = Yb[v][3];
    }
    if (c == 0) {
        lp[(size_t)h * HW + rowa]      = Ysa[0];
        lp[(size_t)h * HW + rowa + 8]  = Ysa[2];
        lp[(size_t)h * HW + rowb]      = Ysb[0];
        lp[(size_t)h * HW + rowb + 8]  = Ysb[2];
    }
}

// ------ combine partials -> normalized bf16 swizzled y tiles (4x parallel) --
// grid (256 blobs, 4 quarters), 128 threads = one pixel row each.
__global__ __launch_bounds__(128) void combine_tiles_kernel(
    const float* __restrict__ ypart, const float* __restrict__ lpart,
    uint8_t* __restrict__ ytiles)
{
    const int blob = blockIdx.x;
    const int qt   = blockIdx.y;           // quarter: 8 channels = 16 bytes
    const int h = blob >> 5, jb = blob & 31;
    const int pix = threadIdx.x;
    const int n = jb * 128 + pix;
    float inv = 1.f / (lpart[(size_t)h * HW + n] +
                       lpart[8 * HW + (size_t)h * HW + n]);
    const float* y0 = ypart + (size_t)(h * 32 + qt * 8) * HW + n;
    const float* y1 = y0 + 256 * HW;
    uint32_t b[4];
    #pragma unroll
    for (int i = 0; i < 4; i++) {
        float lo = (y0[(size_t)(2*i) * HW]   + y1[(size_t)(2*i) * HW])   * inv;
        float hi = (y0[(size_t)(2*i+1) * HW] + y1[(size_t)(2*i+1) * HW]) * inv;
        b[i] = cvt_bf2(hi, lo);
    }
    uint8_t* bp = ytiles + (size_t)blob * 8192;
    *(uint4*)(bp + SW64R(pix * 64 + qt * 16)) = make_uint4(b[0], b[1], b[2], b[3]);
}

// ===== proj GEMM: B from pre-packed y tiles via cp.async ====================
__global__ __launch_bounds__(256) void proj_gemm_kernel(
    const float* __restrict__ A, const uint8_t* __restrict__ ytiles,
    const float* __restrict__ bias, float* __restrict__ C)
{
    __shared__ __align__(128) char sA[8192];
    __shared__ __align__(128) char sB[16384];
    const int t = threadIdx.x, wid = t >> 5, lane = t & 31;
    const int bm = blockIdx.y * 128, bn = blockIdx.x * 128;
    const int K = 256, N = HW;
    const uint32_t ab = smem_u32(sA), bb = smem_u32(sB);

    const int ma = t >> 1, qa = t & 1;

    const int fr = wid * 16 + (lane & 7) + ((lane >> 3) & 1) * 8;
    const uint32_t aA0 = ab + SW64R(fr * 64 + (lane >> 4) * 16);
    const uint32_t aA1 = ab + SW64R(fr * 64 + (2 + (lane >> 4)) * 16);
    const int br = (lane & 7) + (lane >> 4) * 8;
    const uint32_t aB0 = bb + SW64R(br * 64 + ((lane >> 3) & 1) * 16);
    const uint32_t aB1 = bb + SW64R(br * 64 + (2 + ((lane >> 3) & 1)) * 16);

    const uint32_t stA0 = ab + SW64R(ma * 64 + qa * 32);
    const uint32_t stA1 = ab + SW64R(ma * 64 + qa * 32 + 16);

    const uint8_t* ybase = ytiles + (size_t)blockIdx.x * 8192;

    float acc[16][4];
    #pragma unroll
    for (int i = 0; i < 16; i++)
        #pragma unroll
        for (int v = 0; v < 4; v++) acc[i][v] = 0.f;

    float av[16];

    {
        const float* ap = A + (size_t)(bm + ma) * K + qa * 16;
        #pragma unroll
        for (int i = 0; i < 4; i++) {
            float4 x = ((const float4*)ap)[i];
            av[4*i] = x.x; av[4*i+1] = x.y; av[4*i+2] = x.z; av[4*i+3] = x.w;
        }
        uint32_t ua[8];
        #pragma unroll
        for (int i = 0; i < 8; i++) ua[i] = cvt_bf2(av[2*i+1], av[2*i]);
        asm volatile("st.shared.v4.b32 [%0], {%1,%2,%3,%4};"
                     :: "r"(stA0), "r"(ua[0]), "r"(ua[1]), "r"(ua[2]), "r"(ua[3]));
        asm volatile("st.shared.v4.b32 [%0], {%1,%2,%3,%4};"
                     :: "r"(stA1), "r"(ua[4]), "r"(ua[5]), "r"(ua[6]), "r"(ua[7]));
        uint32_t o = t << 4;
        CP16(bb + o,        ybase + o);
        CP16(bb + o + 4096, ybase + o + 4096);
        CPCOMMIT();
        CPWAIT0();
    }
    __syncthreads();

    for (int kt = 0; kt < 8; kt++) {
        if (kt < 7) {
            const float* ap = A + (size_t)(bm + ma) * K + (kt + 1) * 32 + qa * 16;
            #pragma unroll
            for (int i = 0; i < 4; i++) {
                float4 x = ((const float4*)ap)[i];
                av[4*i] = x.x; av[4*i+1] = x.y; av[4*i+2] = x.z; av[4*i+3] = x.w;
            }
            const uint8_t* yb2 = ybase + (size_t)(kt + 1) * 32 * 8192;
            uint32_t nofs = (uint32_t)((kt + 1) & 1) * 8192;
            uint32_t o = t << 4;
            CP16(bb + nofs + o,        yb2 + o);
            CP16(bb + nofs + o + 4096, yb2 + o + 4096);
            CPCOMMIT();
        }

        const uint32_t bofs = (uint32_t)(kt & 1) * 8192;
        uint32_t A0[4], A1[4];
        ldsm4(A0[0], A0[1], A0[2], A0[3], aA0);
        ldsm4(A1[0], A1[1], A1[2], A1[3], aA1);
        #pragma unroll
        for (int nch = 0; nch < 8; nch++) {
            uint32_t b00, b01, b02, b03, b10, b11, b12, b13;
            ldsm4(b00, b01, b02, b03, aB0 + bofs + nch * 1024);
            ldsm4(b10, b11, b12, b13, aB1 + bofs + nch * 1024);
            mma16816(acc[2*nch],   A0, b00, b01);
            mma16816(acc[2*nch],   A1, b10, b11);
            mma16816(acc[2*nch+1], A0, b02, b03);
            mma16816(acc[2*nch+1], A1, b12, b13);
        }
        __syncthreads();
        if (kt < 7) {
            uint32_t ua[8];
            #pragma unroll
            for (int i = 0; i < 8; i++) ua[i] = cvt_bf2(av[2*i+1], av[2*i]);
            asm volatile("st.shared.v4.b32 [%0], {%1,%2,%3,%4};"
                         :: "r"(stA0), "r"(ua[0]), "r"(ua[1]), "r"(ua[2]), "r"(ua[3]));
            asm volatile("st.shared.v4.b32 [%0], {%1,%2,%3,%4};"
                         :: "r"(stA1), "r"(ua[4]), "r"(ua[5]), "r"(ua[6]), "r"(ua[7]));
            CPWAIT0();
        }
        __syncthreads();
    }

    int r0 = bm + wid * 16 + (lane >> 2);
    float bv0 = bias[r0];
    float bv1 = bias[r0 + 8];
    float* c0p = C + (size_t)r0 * N + bn + (lane & 3) * 2;
    float* c1p = C + (size_t)(r0 + 8) * N + bn + (lane & 3) * 2;
    #pragma unroll
    for (int nc = 0; nc < 16; nc++) {
        *(float2*)(c0p + nc * 8) = make_float2(acc[nc][0] + bv0, acc[nc][1] + bv0);
        *(float2*)(c1p + nc * 8) = make_float2(acc[nc][2] + bv1, acc[nc][3] + bv1);
    }
}

// --------------- residual + channel LayerNorm (z cached in regs) ------------
__global__ __launch_bounds__(256) void ln_kernel(
    const float* __restrict__ x, const float* __restrict__ yp,
    const float* __restrict__ gamma, const float* __restrict__ beta,
    float* __restrict__ out)
{
    __shared__ float ssum[8][32], ssq[8][32];
    int nx = threadIdx.x & 31;
    int cg = threadIdx.x >> 5;
    int n  = blockIdx.x * 32 + nx;

    float z[64];
    float sum = 0.f, sq = 0.f;
    #pragma unroll
    for (int i = 0; i < 64; i++) {
        int c = cg + i * 8;
        z[i] = x[(size_t)c * HW + n] + yp[(size_t)c * HW + n];
        sum += z[i]; sq += z[i] * z[i];
    }
    ssum[cg][nx] = sum; ssq[cg][nx] = sq;
    __syncthreads();
    float tot = 0.f, totsq = 0.f;
    #pragma unroll
    for (int g = 0; g < 8; g++) { tot += ssum[g][nx]; totsq += ssq[g][nx]; }
    float mu   = tot * (1.f / 512.f);
    float var  = totsq * (1.f / 512.f) - mu * mu;
    float rstd = rsqrtf(var + 1e-5f);
    #pragma unroll
    for (int i = 0; i < 64; i++) {
        int c = cg + i * 8;
        out[(size_t)c * HW + n] = (z[i] - mu) * rstd * gamma[c] + beta[c];
    }
}

// -----------------------------------------------------------------------------
extern "C" void kernel_launch(void* const* d_in, const int* in_sizes, int n_in,
                              void* d_out, int out_size) {
    const float* x        = (const float*)d_in[0];
    const float* w_qkv    = (const float*)d_in[1];
    const float* w_proj   = (const float*)d_in[2];
    const float* b_proj   = (const float*)d_in[3];
    const float* pos_bias = (const float*)d_in[4];
    const float* gamma    = (const float*)d_in[5];
    const float* beta     = (const float*)d_in[6];
    float* out = (float*)d_out;

    float *proj, *ypart, *lpart;
    uint8_t *tiles, *ytiles;
    uint32_t* posb;
    cudaGetSymbolAddress((void**)&proj,   g_proj);
    cudaGetSymbolAddress((void**)&ypart,  g_ypart);
    cudaGetSymbolAddress((void**)&lpart,  g_lpart);
    cudaGetSymbolAddress((void**)&tiles,  g_tiles);
    cudaGetSymbolAddress((void**)&ytiles, g_ytiles);
    cudaGetSymbolAddress((void**)&posb,   g_posb);

    pos_kernel<<<64, 256>>>(pos_bias, posb);
    qkv_gemm_kernel<<<dim3(32, 6), 256>>>(w_qkv, x, tiles, 512);
    attn_kernel<<<dim3(32, 8, 2), 128>>>(tiles, posb, ypart, lpart);
    combine_tiles_kernel<<<dim3(256, 4), 128>>>(ypart, lpart, ytiles);
    proj_gemm_kernel<<<dim3(32, 4), 256>>>(w_proj, ytiles, b_proj, proj);
    ln_kernel<<<128, 256>>>(x, proj, gamma, beta, out);
}

// round 16
// speedup vs baseline: 1.0903x; 1.0183x over previous
#include <cuda_runtime.h>
#include <cuda_bf16.h>
#include <math.h>
#include <stdint.h>

// ---------------------------------------------------------------------------
// FixFeatureAttention sm_103.  R16: combine+split-K removed — attention is
// single-pass (32 key tiles) and its epilogue normalizes + packs bf16
// swizzled y-tiles directly (smem transpose over the retired sK buffer).
// ln re-blocked for 256 CTAs. 5 launches: pos, qkv, attn, proj, ln.
// ---------------------------------------------------------------------------

#define HW 4096
#define LOG2E 1.4426950408889634f
#define QSCALE 0.17677669529663687f   // 1/sqrt(32)

__device__ float    g_proj[512 * HW];
__device__ uint8_t  g_tiles[6 * 1024 * 1024];   // q/k/v bf16 swizzled tiles
__device__ uint8_t  g_ytiles[2 * 1024 * 1024];  // normalized y bf16 tiles
__device__ uint32_t g_posb[8 * 2048];

#define SW64R(o) ((o) ^ ((((o) >> 7) & 3) << 4))

__device__ __forceinline__ uint32_t smem_u32(const void* p) {
    uint32_t a;
    asm("{.reg .u64 t; cvta.to.shared.u64 t, %1; cvt.u32.u64 %0, t;}" : "=r"(a) : "l"(p));
    return a;
}
__device__ __forceinline__ uint32_t cvt_bf2(float hi, float lo) {
    uint32_t r;
    asm("cvt.rn.bf16x2.f32 %0, %1, %2;" : "=r"(r) : "f"(hi), "f"(lo));
    return r;
}
__device__ __forceinline__ void ldsm4(uint32_t& r0, uint32_t& r1, uint32_t& r2,
                                      uint32_t& r3, uint32_t a) {
    asm volatile("ldmatrix.sync.aligned.m8n8.x4.shared.b16 {%0,%1,%2,%3}, [%4];"
                 : "=r"(r0), "=r"(r1), "=r"(r2), "=r"(r3) : "r"(a));
}
__device__ __forceinline__ void ldsm4t(uint32_t& r0, uint32_t& r1, uint32_t& r2,
                                       uint32_t& r3, uint32_t a) {
    asm volatile("ldmatrix.sync.aligned.m8n8.x4.trans.shared.b16 {%0,%1,%2,%3}, [%4];"
                 : "=r"(r0), "=r"(r1), "=r"(r2), "=r"(r3) : "r"(a));
}
__device__ __forceinline__ void mma16816(float* c, const uint32_t* a,
                                         uint32_t b0, uint32_t b1) {
    asm("mma.sync.aligned.m16n8k16.row.col.f32.bf16.bf16.f32 "
        "{%0,%1,%2,%3},{%4,%5,%6,%7},{%8,%9},{%0,%1,%2,%3};"
        : "+f"(c[0]), "+f"(c[1]), "+f"(c[2]), "+f"(c[3])
        : "r"(a[0]), "r"(a[1]), "r"(a[2]), "r"(a[3]), "r"(b0), "r"(b1));
}
#define CP16(dst, src) asm volatile("cp.async.cg.shared.global [%0], [%1], 16;" \
                                    :: "r"(dst), "l"(src) : "memory")
#define CPCOMMIT()     asm volatile("cp.async.commit_group;" ::: "memory")
#define CPWAIT0()      asm volatile("cp.async.wait_group 0;" ::: "memory")

__device__ __forceinline__ uint32_t pexp2(uint32_t xu, uint32_t posu) {
    uint32_t x, t, u, f, p, q;
    asm("add.rn.bf16x2 %0, %1, %2;" : "=r"(x) : "r"(xu), "r"(posu));
    asm("add.rn.bf16x2 %0, %1, %2;" : "=r"(t) : "r"(x), "r"(0x43404340u));
    asm("sub.rn.bf16x2 %0, %1, %2;" : "=r"(u) : "r"(t), "r"(0x43404340u));
    asm("sub.rn.bf16x2 %0, %1, %2;" : "=r"(f) : "r"(x), "r"(u));
    asm("fma.rn.bf16x2 %0, %1, %2, %3;" : "=r"(p)
        : "r"(0x3E783E78u), "r"(f), "r"(0x3F343F34u));
    asm("fma.rn.bf16x2 %0, %1, %2, %3;" : "=r"(q)
        : "r"(p), "r"(f), "r"(0x3F803F80u));
    return (t & 0x007F007Fu) * 128u + q + 0xDFFFE000u;
}

// ----------------- pos bias bilinear 16->64, packed bf16x2 (xLOG2E) ---------
__global__ void pos_kernel(const float* __restrict__ pb, uint32_t* __restrict__ posb) {
    int i = blockIdx.x * 256 + threadIdx.x;
    if (i >= 8 * 2048) return;
    int h = i >> 11, jp = i & 2047;
    float v[2];
    #pragma unroll
    for (int s = 0; s < 2; s++) {
        int j = jp * 2 + s;
        int py = j >> 6, px = j & 63;
        float sy = (py + 0.5f) * 0.25f - 0.5f;
        float sx = (px + 0.5f) * 0.25f - 0.5f;
        float fy0 = floorf(sy), fx0 = floorf(sx);
        float wy = sy - fy0, wx = sx - fx0;
        int y0 = max((int)fy0, 0), y1 = min((int)fy0 + 1, 15);
        int x0 = max((int)fx0, 0), x1 = min((int)fx0 + 1, 15);
        const float* p = pb + h * 256;
        float v00 = p[y0 * 16 + x0], v01 = p[y0 * 16 + x1];
        float v10 = p[y1 * 16 + x0], v11 = p[y1 * 16 + x1];
        float va = v00 + (v01 - v00) * wx;
        float vb = v10 + (v11 - v10) * wx;
        v[s] = (va + (vb - va) * wy) * LOG2E;
    }
    posb[i] = cvt_bf2(v[1], v[0]);
}

// ============ qkv GEMM: C = w_qkv * x, fused bf16 tile pack =================
__global__ __launch_bounds__(256) void qkv_gemm_kernel(
    const float* __restrict__ A, const float* __restrict__ B,
    uint8_t* __restrict__ tiles, int K)
{
    __shared__ __align__(128) char sA[8192];
    __shared__ __align__(128) char sB[8192];
    __shared__ __align__(16)  float sT[32][132];
    const int t = threadIdx.x, wid = t >> 5, lane = t & 31;
    const int bm = blockIdx.y * 128, bn = blockIdx.x * 128;
    const uint32_t ab = smem_u32(sA), bb = smem_u32(sB);

    const int ma = t >> 1, qa = t & 1;
    const int nb = t & 127, kh = t >> 7;

    const int fr = wid * 16 + (lane & 7) + ((lane >> 3) & 1) * 8;
    const uint32_t aA0 = ab + SW64R(fr * 64 + (lane >> 4) * 16);
    const uint32_t aA1 = ab + SW64R(fr * 64 + (2 + (lane >> 4)) * 16);
    const int br = (lane & 7) + (lane >> 4) * 8;
    const uint32_t aB0 = bb + SW64R(br * 64 + ((lane >> 3) & 1) * 16);
    const uint32_t aB1 = bb + SW64R(br * 64 + (2 + ((lane >> 3) & 1)) * 16);

    const uint32_t stA0 = ab + SW64R(ma * 64 + qa * 32);
    const uint32_t stA1 = ab + SW64R(ma * 64 + qa * 32 + 16);
    const uint32_t stB0 = bb + SW64R(nb * 64 + kh * 32);
    const uint32_t stB1 = bb + SW64R(nb * 64 + kh * 32 + 16);

    float acc[16][4];
    #pragma unroll
    for (int i = 0; i < 16; i++)
        #pragma unroll
        for (int v = 0; v < 4; v++) acc[i][v] = 0.f;

    const int ntiles = K >> 5;
    float av[16], bv[16];

    {
        const float* ap = A + (size_t)(bm + ma) * K + qa * 16;
        #pragma unroll
        for (int i = 0; i < 4; i++) {
            float4 x = ((const float4*)ap)[i];
            av[4*i] = x.x; av[4*i+1] = x.y; av[4*i+2] = x.z; av[4*i+3] = x.w;
        }
        const float* bp = B + (size_t)(kh * 16) * HW + bn + nb;
        #pragma unroll
        for (int i = 0; i < 16; i++) bv[i] = bp[(size_t)i * HW];
        uint32_t ua[8], ub[8];
        #pragma unroll
        for (int i = 0; i < 8; i++) {
            ua[i] = cvt_bf2(av[2*i+1], av[2*i]);
            ub[i] = cvt_bf2(bv[2*i+1], bv[2*i]);
        }
        asm volatile("st.shared.v4.b32 [%0], {%1,%2,%3,%4};"
                     :: "r"(stA0), "r"(ua[0]), "r"(ua[1]), "r"(ua[2]), "r"(ua[3]));
        asm volatile("st.shared.v4.b32 [%0], {%1,%2,%3,%4};"
                     :: "r"(stA1), "r"(ua[4]), "r"(ua[5]), "r"(ua[6]), "r"(ua[7]));
        asm volatile("st.shared.v4.b32 [%0], {%1,%2,%3,%4};"
                     :: "r"(stB0), "r"(ub[0]), "r"(ub[1]), "r"(ub[2]), "r"(ub[3]));
        asm volatile("st.shared.v4.b32 [%0], {%1,%2,%3,%4};"
                     :: "r"(stB1), "r"(ub[4]), "r"(ub[5]), "r"(ub[6]), "r"(ub[7]));
    }
    __syncthreads();

    for (int kt = 0; kt < ntiles; kt++) {
        if (kt + 1 < ntiles) {
            int k0 = (kt + 1) * 32;
            const float* ap = A + (size_t)(bm + ma) * K + k0 + qa * 16;
            #pragma unroll
            for (int i = 0; i < 4; i++) {
                float4 x = ((const float4*)ap)[i];
                av[4*i] = x.x; av[4*i+1] = x.y; av[4*i+2] = x.z; av[4*i+3] = x.w;
            }
            const float* bp = B + (size_t)(k0 + kh * 16) * HW + bn + nb;
            #pragma unroll
            for (int i = 0; i < 16; i++) bv[i] = bp[(size_t)i * HW];
        }

        uint32_t A0[4], A1[4];
        ldsm4(A0[0], A0[1], A0[2], A0[3], aA0);
        ldsm4(A1[0], A1[1], A1[2], A1[3], aA1);
        #pragma unroll
        for (int nch = 0; nch < 8; nch++) {
            uint32_t b00, b01, b02, b03, b10, b11, b12, b13;
            ldsm4(b00, b01, b02, b03, aB0 + nch * 1024);
            ldsm4(b10, b11, b12, b13, aB1 + nch * 1024);
            mma16816(acc[2*nch],   A0, b00, b01);
            mma16816(acc[2*nch],   A1, b10, b11);
            mma16816(acc[2*nch+1], A0, b02, b03);
            mma16816(acc[2*nch+1], A1, b12, b13);
        }
        __syncthreads();
        if (kt + 1 < ntiles) {
            uint32_t ua[8], ub[8];
            #pragma unroll
            for (int i = 0; i < 8; i++) {
                ua[i] = cvt_bf2(av[2*i+1], av[2*i]);
                ub[i] = cvt_bf2(bv[2*i+1], bv[2*i]);
            }
            asm volatile("st.shared.v4.b32 [%0], {%1,%2,%3,%4};"
                         :: "r"(stA0), "r"(ua[0]), "r"(ua[1]), "r"(ua[2]), "r"(ua[3]));
            asm volatile("st.shared.v4.b32 [%0], {%1,%2,%3,%4};"
                         :: "r"(stA1), "r"(ua[4]), "r"(ua[5]), "r"(ua[6]), "r"(ua[7]));
            asm volatile("st.shared.v4.b32 [%0], {%1,%2,%3,%4};"
                         :: "r"(stB0), "r"(ub[0]), "r"(ub[1]), "r"(ub[2]), "r"(ub[3]));
            asm volatile("st.shared.v4.b32 [%0], {%1,%2,%3,%4};"
                         :: "r"(stB1), "r"(ub[4]), "r"(ub[5]), "r"(ub[6]), "r"(ub[7]));
        }
        __syncthreads();
    }

    const int g2 = lane >> 2, q2 = lane & 3;
    const int chA = wid * 16 + g2;
    const int type = bm >> 8;
    const float esc = (type == 0) ? (QSCALE * LOG2E) : 1.0f;
    uint8_t* tbase = tiles + (size_t)(type * 8) * 32 * 8192 + (size_t)blockIdx.x * 8192;

    #pragma unroll
    for (int p0 = 0; p0 < 128; p0 += 32) {
        __syncthreads();
        #pragma unroll
        for (int t2 = 0; t2 < 4; t2++) {
            int nc  = (p0 >> 3) + t2;
            int pxl = nc * 8 + q2 * 2 - p0;
            sT[pxl][chA]         = acc[nc][0];
            sT[pxl + 1][chA]     = acc[nc][1];
            sT[pxl][chA + 8]     = acc[nc][2];
            sT[pxl + 1][chA + 8] = acc[nc][3];
        }
        __syncthreads();
        int pxl = t >> 3;
        int pixrow = p0 + pxl;
        #pragma unroll
        for (int s = 0; s < 2; s++) {
            int w = (t & 7) + s * 8;
            int hh = ((bm & 255) >> 5) + (w >> 2);
            int d0 = (w & 3) * 8;
            float4 f0 = *(float4*)&sT[pxl][w * 8];
            float4 f1 = *(float4*)&sT[pxl][w * 8 + 4];
            uint32_t b0 = cvt_bf2(f0.y * esc, f0.x * esc);
            uint32_t b1 = cvt_bf2(f0.w * esc, f0.z * esc);
            uint32_t b2 = cvt_bf2(f1.y * esc, f1.x * esc);
            uint32_t b3 = cvt_bf2(f1.w * esc, f1.z * esc);
            uint8_t* blob = tbase + (size_t)hh * 32 * 8192;
            *(uint4*)(blob + SW64R(pixrow * 64 + d0 * 2)) = make_uint4(b0, b1, b2, b3);
        }
    }
}

// ====== flash attention, single pass, fused normalize+pack epilogue =========
__global__ __launch_bounds__(128, 4) void attn_kernel(
    const uint8_t* __restrict__ tiles, const uint32_t* __restrict__ posb,
    uint8_t* __restrict__ ytiles)
{
    __shared__ __align__(128) char sQ[8192];
    __shared__ __align__(128) char sK[16384];
    __shared__ __align__(128) char sV[16384];
    __shared__ __align__(16)  char sPos[512];

    const int tid  = threadIdx.x;
    const int wid  = tid >> 5;
    const int lane = tid & 31;
    const int g    = lane >> 2;
    const int c    = lane & 3;
    const int h    = blockIdx.y;

    const uint32_t qb = smem_u32(sQ), kb = smem_u32(sK), vb = smem_u32(sV);
    const uint32_t pbs = smem_u32(sPos);

    const uint8_t* tQ = tiles + (size_t)(h * 32 + blockIdx.x) * 8192;
    const uint8_t* tK = tiles + (size_t)((8 + h) * 32) * 8192;
    const uint8_t* tV = tiles + (size_t)((16 + h) * 32) * 8192;
    const uint8_t* tP = (const uint8_t*)(posb + h * 2048);

    {
        uint32_t o = tid << 4;
        #pragma unroll
        for (int s = 0; s < 4; s++) {
            CP16(qb + o + s * 2048, tQ + o + s * 2048);
            CP16(kb + o + s * 2048, tK + o + s * 2048);
            CP16(vb + o + s * 2048, tV + o + s * 2048);
        }
        if (tid < 16) CP16(pbs + (tid << 4), tP + (tid << 4));
        CPCOMMIT();
        CPWAIT0();
    }
    __syncthreads();

    uint32_t QAa0[4], QAa1[4], QAb0[4], QAb1[4];
    {
        int rowa = wid * 32 + (lane & 7) + ((lane >> 3) & 1) * 8;
        int ch   = lane >> 4;
        ldsm4(QAa0[0], QAa0[1], QAa0[2], QAa0[3], qb + SW64R(rowa * 64 + ch * 16));
        ldsm4(QAa1[0], QAa1[1], QAa1[2], QAa1[3], qb + SW64R(rowa * 64 + (2 + ch) * 16));
        int rowb = rowa + 16;
        ldsm4(QAb0[0], QAb0[1], QAb0[2], QAb0[3], qb + SW64R(rowb * 64 + ch * 16));
        ldsm4(QAb1[0], QAb1[1], QAb1[2], QAb1[3], qb + SW64R(rowb * 64 + (2 + ch) * 16));
    }
    uint32_t aK0, aK1, aV0, aV1;
    {
        int ko = (lane & 7) + (lane >> 4) * 8;
        int ch = (lane >> 3) & 1;
        aK0 = kb + SW64R(ko * 64 + ch * 16);
        aK1 = kb + SW64R(ko * 64 + (2 + ch) * 16);
    }
    {
        int ko = (lane & 7) + ((lane >> 3) & 1) * 8;
        int ch = lane >> 4;
        aV0 = vb + SW64R(ko * 64 + ch * 16);
        aV1 = vb + SW64R(ko * 64 + (2 + ch) * 16);
    }

    const uint32_t bOne = (lane < 4) ? 0x3F803F80u : 0u;
    float Ya[4][4], Yb[4][4], Ysa[4], Ysb[4];
    #pragma unroll
    for (int u = 0; u < 4; u++) {
        Ysa[u] = 0.f; Ysb[u] = 0.f;
        #pragma unroll
        for (int v = 0; v < 4; v++) { Ya[u][v] = 0.f; Yb[u][v] = 0.f; }
    }

    uint32_t kf[2][8];

    for (int it = 0; it < 32; it++) {
        const uint32_t bofs = (uint32_t)(it & 1) * 8192;

        if (it < 31) {
            const uint32_t nofs = (uint32_t)((it + 1) & 1) * 8192;
            const size_t jo = (size_t)(it + 1) * 8192;
            uint32_t o = tid << 4;
            #pragma unroll
            for (int s = 0; s < 4; s++) {
                CP16(kb + nofs + o + s * 2048, tK + jo + o + s * 2048);
                CP16(vb + nofs + o + s * 2048, tV + jo + o + s * 2048);
            }
            if (tid < 16)
                CP16(pbs + (((it + 1) & 1) << 8) + (tid << 4),
                     tP + (size_t)(it + 1) * 256 + (tid << 4));
            CPCOMMIT();
        }

        const uint32_t kA0 = aK0 + bofs, kA1 = aK1 + bofs;
        const uint32_t vA0 = aV0 + bofs, vA1 = aV1 + bofs;
        const uint32_t* sp = (const uint32_t*)(sPos + (it & 1) * 256);

        ldsm4(kf[0][0], kf[0][1], kf[0][2], kf[0][3], kA0);
        ldsm4(kf[0][4], kf[0][5], kf[0][6], kf[0][7], kA1);

        #pragma unroll
        for (int j = 0; j < 8; j++) {
            const uint32_t* kc = kf[j & 1];
            uint32_t* kn = kf[(j + 1) & 1];

            uint32_t pos0 = sp[j * 8 + c];
            uint32_t pos1 = sp[j * 8 + 4 + c];

            uint32_t v0, v1, v2, v3, w0, w1, w2, w3;
            ldsm4t(v0, v1, v2, v3, vA0 + j * 1024);
            ldsm4t(w0, w1, w2, w3, vA1 + j * 1024);
            if (j < 7) {
                ldsm4(kn[0], kn[1], kn[2], kn[3], kA0 + (j + 1) * 1024);
                ldsm4(kn[4], kn[5], kn[6], kn[7], kA1 + (j + 1) * 1024);
            }

            float Ca0[4] = {0.f,0.f,0.f,0.f}, Ca1[4] = {0.f,0.f,0.f,0.f};
            float Cb0[4] = {0.f,0.f,0.f,0.f}, Cb1[4] = {0.f,0.f,0.f,0.f};
            mma16816(Ca0, QAa0, kc[0], kc[1]);
            mma16816(Ca0, QAa1, kc[4], kc[5]);
            mma16816(Ca1, QAa0, kc[2], kc[3]);
            mma16816(Ca1, QAa1, kc[6], kc[7]);
            mma16816(Cb0, QAb0, kc[0], kc[1]);
            mma16816(Cb0, QAb1, kc[4], kc[5]);
            mma16816(Cb1, QAb0, kc[2], kc[3]);
            mma16816(Cb1, QAb1, kc[6], kc[7]);

            uint32_t Pa[4], Pb[4];
            Pa[0] = pexp2(cvt_bf2(Ca0[1], Ca0[0]), pos0);
            Pa[1] = pexp2(cvt_bf2(Ca0[3], Ca0[2]), pos0);
            Pa[2] = pexp2(cvt_bf2(Ca1[1], Ca1[0]), pos1);
            Pa[3] = pexp2(cvt_bf2(Ca1[3], Ca1[2]), pos1);
            Pb[0] = pexp2(cvt_bf2(Cb0[1], Cb0[0]), pos0);
            Pb[1] = pexp2(cvt_bf2(Cb0[3], Cb0[2]), pos0);
            Pb[2] = pexp2(cvt_bf2(Cb1[1], Cb1[0]), pos1);
            Pb[3] = pexp2(cvt_bf2(Cb1[3], Cb1[2]), pos1);

            mma16816(Ya[0], Pa, v0, v1);
            mma16816(Ya[1], Pa, v2, v3);
            mma16816(Ya[2], Pa, w0, w1);
            mma16816(Ya[3], Pa, w2, w3);
            mma16816(Ysa,   Pa, bOne, bOne);
            mma16816(Yb[0], Pb, v0, v1);
            mma16816(Yb[1], Pb, v2, v3);
            mma16816(Yb[2], Pb, w0, w1);
            mma16816(Yb[3], Pb, w2, w3);
            mma16816(Ysb,   Pb, bOne, bOne);
        }

        if (it < 31) CPWAIT0();
        __syncthreads();
    }

    // ---- fused epilogue: normalize, transpose via sK overlay, pack tiles ----
    float iAa = 1.f / __shfl_sync(0xffffffffu, Ysa[0], lane & 28);
    float iBa = 1.f / __shfl_sync(0xffffffffu, Ysa[2], lane & 28);
    float iAb = 1.f / __shfl_sync(0xffffffffu, Ysb[0], lane & 28);
    float iBb = 1.f / __shfl_sync(0xffffffffu, Ysb[2], lane & 28);

    float* sT = (float*)sK;                       // 64 x 33 floats per pass
    uint8_t* blob = ytiles + (size_t)(h * 32 + blockIdx.x) * 8192;
    const int rla = (wid & 1) * 32 + g;           // row within 64-pixel pass

    #pragma unroll
    for (int pass = 0; pass < 2; pass++) {
        if ((wid >> 1) == pass) {
            #pragma unroll
            for (int v = 0; v < 4; v++) {
                int ch = v * 8 + 2 * c;
                sT[rla * 33 + ch]            = Ya[v][0] * iAa;
                sT[rla * 33 + ch + 1]        = Ya[v][1] * iAa;
                sT[(rla + 8) * 33 + ch]      = Ya[v][2] * iBa;
                sT[(rla + 8) * 33 + ch + 1]  = Ya[v][3] * iBa;
                sT[(rla + 16) * 33 + ch]     = Yb[v][0] * iAb;
                sT[(rla + 16) * 33 + ch + 1] = Yb[v][1] * iAb;
                sT[(rla + 24) * 33 + ch]     = Yb[v][2] * iBb;
                sT[(rla + 24) * 33 + ch + 1] = Yb[v][3] * iBb;
            }
        }
        __syncthreads();
        {
            int pr   = tid >> 1;                  // pixel within pass
            int half = tid & 1;                   // channel half (16 ch)
            int pix  = pass * 64 + pr;
            const float* row = sT + pr * 33 + half * 16;
            uint32_t b[8];
            #pragma unroll
            for (int i = 0; i < 8; i++)
                b[i] = cvt_bf2(row[2*i + 1], row[2*i]);
            *(uint4*)(blob + SW64R(pix * 64 + half * 32)) =
                make_uint4(b[0], b[1], b[2], b[3]);
            *(uint4*)(blob + SW64R(pix * 64 + half * 32 + 16)) =
                make_uint4(b[4], b[5], b[6], b[7]);
        }
        __syncthreads();
    }
}

// ===== proj GEMM: B from pre-packed y tiles via cp.async ====================
__global__ __launch_bounds__(256) void proj_gemm_kernel(
    const float* __restrict__ A, const uint8_t* __restrict__ ytiles,
    const float* __restrict__ bias, float* __restrict__ C)
{
    __shared__ __align__(128) char sA[8192];
    __shared__ __align__(128) char sB[16384];
    const int t = threadIdx.x, wid = t >> 5, lane = t & 31;
    const int bm = blockIdx.y * 128, bn = blockIdx.x * 128;
    const int K = 256, N = HW;
    const uint32_t ab = smem_u32(sA), bb = smem_u32(sB);

    const int ma = t >> 1, qa = t & 1;

    const int fr = wid * 16 + (lane & 7) + ((lane >> 3) & 1) * 8;
    const uint32_t aA0 = ab + SW64R(fr * 64 + (lane >> 4) * 16);
    const uint32_t aA1 = ab + SW64R(fr * 64 + (2 + (lane >> 4)) * 16);
    const int br = (lane & 7) + (lane >> 4) * 8;
    const uint32_t aB0 = bb + SW64R(br * 64 + ((lane >> 3) & 1) * 16);
    const uint32_t aB1 = bb + SW64R(br * 64 + (2 + ((lane >> 3) & 1)) * 16);

    const uint32_t stA0 = ab + SW64R(ma * 64 + qa * 32);
    const uint32_t stA1 = ab + SW64R(ma * 64 + qa * 32 + 16);

    const uint8_t* ybase = ytiles + (size_t)blockIdx.x * 8192;

    float acc[16][4];
    #pragma unroll
    for (int i = 0; i < 16; i++)
        #pragma unroll
        for (int v = 0; v < 4; v++) acc[i][v] = 0.f;

    float av[16];

    {
        const float* ap = A + (size_t)(bm + ma) * K + qa * 16;
        #pragma unroll
        for (int i = 0; i < 4; i++) {
            float4 x = ((const float4*)ap)[i];
            av[4*i] = x.x; av[4*i+1] = x.y; av[4*i+2] = x.z; av[4*i+3] = x.w;
        }
        uint32_t ua[8];
        #pragma unroll
        for (int i = 0; i < 8; i++) ua[i] = cvt_bf2(av[2*i+1], av[2*i]);
        asm volatile("st.shared.v4.b32 [%0], {%1,%2,%3,%4};"
                     :: "r"(stA0), "r"(ua[0]), "r"(ua[1]), "r"(ua[2]), "r"(ua[3]));
        asm volatile("st.shared.v4.b32 [%0], {%1,%2,%3,%4};"
                     :: "r"(stA1), "r"(ua[4]), "r"(ua[5]), "r"(ua[6]), "r"(ua[7]));
        uint32_t o = t << 4;
        CP16(bb + o,        ybase + o);
        CP16(bb + o + 4096, ybase + o + 4096);
        CPCOMMIT();
        CPWAIT0();
    }
    __syncthreads();

    for (int kt = 0; kt < 8; kt++) {
        if (kt < 7) {
            const float* ap = A + (size_t)(bm + ma) * K + (kt + 1) * 32 + qa * 16;
            #pragma unroll
            for (int i = 0; i < 4; i++) {
                float4 x = ((const float4*)ap)[i];
                av[4*i] = x.x; av[4*i+1] = x.y; av[4*i+2] = x.z; av[4*i+3] = x.w;
            }
            const uint8_t* yb2 = ybase + (size_t)(kt + 1) * 32 * 8192;
            uint32_t nofs = (uint32_t)((kt + 1) & 1) * 8192;
            uint32_t o = t << 4;
            CP16(bb + nofs + o,        yb2 + o);
            CP16(bb + nofs + o + 4096, yb2 + o + 4096);
            CPCOMMIT();
        }

        const uint32_t bofs = (uint32_t)(kt & 1) * 8192;
        uint32_t A0[4], A1[4];
        ldsm4(A0[0], A0[1], A0[2], A0[3], aA0);
        ldsm4(A1[0], A1[1], A1[2], A1[3], aA1);
        #pragma unroll
        for (int nch = 0; nch < 8; nch++) {
            uint32_t b00, b01, b02, b03, b10, b11, b12, b13;
            ldsm4(b00, b01, b02, b03, aB0 + bofs + nch * 1024);
            ldsm4(b10, b11, b12, b13, aB1 + bofs + nch * 1024);
            mma16816(acc[2*nch],   A0, b00, b01);
            mma16816(acc[2*nch],   A1, b10, b11);
            mma16816(acc[2*nch+1], A0, b02, b03);
            mma16816(acc[2*nch+1], A1, b12, b13);
        }
        __syncthreads();
        if (kt < 7) {
            uint32_t ua[8];
            #pragma unroll
            for (int i = 0; i < 8; i++) ua[i] = cvt_bf2(av[2*i+1], av[2*i]);
            asm volatile("st.shared.v4.b32 [%0], {%1,%2,%3,%4};"
                         :: "r"(stA0), "r"(ua[0]), "r"(ua[1]), "r"(ua[2]), "r"(ua[3]));
            asm volatile("st.shared.v4.b32 [%0], {%1,%2,%3,%4};"
                         :: "r"(stA1), "r"(ua[4]), "r"(ua[5]), "r"(ua[6]), "r"(ua[7]));
            CPWAIT0();
        }
        __syncthreads();
    }

    int r0 = bm + wid * 16 + (lane >> 2);
    float bv0 = bias[r0];
    float bv1 = bias[r0 + 8];
    float* c0p = C + (size_t)r0 * N + bn + (lane & 3) * 2;
    float* c1p = C + (size_t)(r0 + 8) * N + bn + (lane & 3) * 2;
    #pragma unroll
    for (int nc = 0; nc < 16; nc++) {
        *(float2*)(c0p + nc * 8) = make_float2(acc[nc][0] + bv0, acc[nc][1] + bv0);
        *(float2*)(c1p + nc * 8) = make_float2(acc[nc][2] + bv1, acc[nc][3] + bv1);
    }
}

// ------- residual + channel LayerNorm: 256 CTAs, 16 px x 16 groups ----------
__global__ __launch_bounds__(256) void ln_kernel(
    const float* __restrict__ x, const float* __restrict__ yp,
    const float* __restrict__ gamma, const float* __restrict__ beta,
    float* __restrict__ out)
{
    __shared__ float ssum[16][16], ssq[16][16];
    int nx = threadIdx.x & 15;
    int cg = threadIdx.x >> 4;
    int n  = blockIdx.x * 16 + nx;

    float z[32];
    float sum = 0.f, sq = 0.f;
    #pragma unroll
    for (int i = 0; i < 32; i++) {
        int c = cg + i * 16;
        z[i] = x[(size_t)c * HW + n] + yp[(size_t)c * HW + n];
        sum += z[i]; sq += z[i] * z[i];
    }
    ssum[cg][nx] = sum; ssq[cg][nx] = sq;
    __syncthreads();
    float tot = 0.f, totsq = 0.f;
    #pragma unroll
    for (int g = 0; g < 16; g++) { tot += ssum[g][nx]; totsq += ssq[g][nx]; }
    float mu   = tot * (1.f / 512.f);
    float var  = totsq * (1.f / 512.f) - mu * mu;
    float rstd = rsqrtf(var + 1e-5f);
    #pragma unroll
    for (int i = 0; i < 32; i++) {
        int c = cg + i * 16;
        out[(size_t)c * HW + n] = (z[i] - mu) * rstd * gamma[c] + beta[c];
    }
}

// -----------------------------------------------------------------------------
extern "C" void kernel_launch(void* const* d_in, const int* in_sizes, int n_in,
                              void* d_out, int out_size) {
    const float* x        = (const float*)d_in[0];
    const float* w_qkv    = (const float*)d_in[1];
    const float* w_proj   = (const float*)d_in[2];
    const float* b_proj   = (const float*)d_in[3];
    const float* pos_bias = (const float*)d_in[4];
    const float* gamma    = (const float*)d_in[5];
    const float* beta     = (const float*)d_in[6];
    float* out = (float*)d_out;

    float* proj;
    uint8_t *tiles, *ytiles;
    uint32_t* posb;
    cudaGetSymbolAddress((void**)&proj,   g_proj);
    cudaGetSymbolAddress((void**)&tiles,  g_tiles);
    cudaGetSymbolAddress((void**)&ytiles, g_ytiles);
    cudaGetSymbolAddress((void**)&posb,   g_posb);

    pos_kernel<<<64, 256>>>(pos_bias, posb);
    qkv_gemm_kernel<<<dim3(32, 6), 256>>>(w_qkv, x, tiles, 512);
    attn_kernel<<<dim3(32, 8), 128>>>(tiles, posb, ytiles);
    proj_gemm_kernel<<<dim3(32, 4), 256>>>(w_proj, ytiles, b_proj, proj);
    ln_kernel<<<256, 256>>>(x, proj, gamma, beta, out);
}

// round 17
// speedup vs baseline: 1.0928x; 1.0023x over previous
#include <cuda_runtime.h>
#include <cuda_bf16.h>
#include <math.h>
#include <stdint.h>

// ---------------------------------------------------------------------------
// FixFeatureAttention sm_103.  R17 = R16 with proj GEMM restructured: ALL 8
// B-blobs (64KB) cp.async'd once in the prologue (dynamic smem), zero waits
// in the mainloop. attn/qkv/ln/pos unchanged.
// ---------------------------------------------------------------------------

#define HW 4096
#define LOG2E 1.4426950408889634f
#define QSCALE 0.17677669529663687f   // 1/sqrt(32)

__device__ float    g_proj[512 * HW];
__device__ uint8_t  g_tiles[6 * 1024 * 1024];   // q/k/v bf16 swizzled tiles
__device__ uint8_t  g_ytiles[2 * 1024 * 1024];  // normalized y bf16 tiles
__device__ uint32_t g_posb[8 * 2048];

#define SW64R(o) ((o) ^ ((((o) >> 7) & 3) << 4))

__device__ __forceinline__ uint32_t smem_u32(const void* p) {
    uint32_t a;
    asm("{.reg .u64 t; cvta.to.shared.u64 t, %1; cvt.u32.u64 %0, t;}" : "=r"(a) : "l"(p));
    return a;
}
__device__ __forceinline__ uint32_t cvt_bf2(float hi, float lo) {
    uint32_t r;
    asm("cvt.rn.bf16x2.f32 %0, %1, %2;" : "=r"(r) : "f"(hi), "f"(lo));
    return r;
}
__device__ __forceinline__ void ldsm4(uint32_t& r0, uint32_t& r1, uint32_t& r2,
                                      uint32_t& r3, uint32_t a) {
    asm volatile("ldmatrix.sync.aligned.m8n8.x4.shared.b16 {%0,%1,%2,%3}, [%4];"
                 : "=r"(r0), "=r"(r1), "=r"(r2), "=r"(r3) : "r"(a));
}
__device__ __forceinline__ void ldsm4t(uint32_t& r0, uint32_t& r1, uint32_t& r2,
                                       uint32_t& r3, uint32_t a) {
    asm volatile("ldmatrix.sync.aligned.m8n8.x4.trans.shared.b16 {%0,%1,%2,%3}, [%4];"
                 : "=r"(r0), "=r"(r1), "=r"(r2), "=r"(r3) : "r"(a));
}
__device__ __forceinline__ void mma16816(float* c, const uint32_t* a,
                                         uint32_t b0, uint32_t b1) {
    asm("mma.sync.aligned.m16n8k16.row.col.f32.bf16.bf16.f32 "
        "{%0,%1,%2,%3},{%4,%5,%6,%7},{%8,%9},{%0,%1,%2,%3};"
        : "+f"(c[0]), "+f"(c[1]), "+f"(c[2]), "+f"(c[3])
        : "r"(a[0]), "r"(a[1]), "r"(a[2]), "r"(a[3]), "r"(b0), "r"(b1));
}
#define CP16(dst, src) asm volatile("cp.async.cg.shared.global [%0], [%1], 16;" \
                                    :: "r"(dst), "l"(src) : "memory")
#define CPCOMMIT()     asm volatile("cp.async.commit_group;" ::: "memory")
#define CPWAIT0()      asm volatile("cp.async.wait_group 0;" ::: "memory")

__device__ __forceinline__ uint32_t pexp2(uint32_t xu, uint32_t posu) {
    uint32_t x, t, u, f, p, q;
    asm("add.rn.bf16x2 %0, %1, %2;" : "=r"(x) : "r"(xu), "r"(posu));
    asm("add.rn.bf16x2 %0, %1, %2;" : "=r"(t) : "r"(x), "r"(0x43404340u));
    asm("sub.rn.bf16x2 %0, %1, %2;" : "=r"(u) : "r"(t), "r"(0x43404340u));
    asm("sub.rn.bf16x2 %0, %1, %2;" : "=r"(f) : "r"(x), "r"(u));
    asm("fma.rn.bf16x2 %0, %1, %2, %3;" : "=r"(p)
        : "r"(0x3E783E78u), "r"(f), "r"(0x3F343F34u));
    asm("fma.rn.bf16x2 %0, %1, %2, %3;" : "=r"(q)
        : "r"(p), "r"(f), "r"(0x3F803F80u));
    return (t & 0x007F007Fu) * 128u + q + 0xDFFFE000u;
}

// ----------------- pos bias bilinear 16->64, packed bf16x2 (xLOG2E) ---------
__global__ void pos_kernel(const float* __restrict__ pb, uint32_t* __restrict__ posb) {
    int i = blockIdx.x * 256 + threadIdx.x;
    if (i >= 8 * 2048) return;
    int h = i >> 11, jp = i & 2047;
    float v[2];
    #pragma unroll
    for (int s = 0; s < 2; s++) {
        int j = jp * 2 + s;
        int py = j >> 6, px = j & 63;
        float sy = (py + 0.5f) * 0.25f - 0.5f;
        float sx = (px + 0.5f) * 0.25f - 0.5f;
        float fy0 = floorf(sy), fx0 = floorf(sx);
        float wy = sy - fy0, wx = sx - fx0;
        int y0 = max((int)fy0, 0), y1 = min((int)fy0 + 1, 15);
        int x0 = max((int)fx0, 0), x1 = min((int)fx0 + 1, 15);
        const float* p = pb + h * 256;
        float v00 = p[y0 * 16 + x0], v01 = p[y0 * 16 + x1];
        float v10 = p[y1 * 16 + x0], v11 = p[y1 * 16 + x1];
        float va = v00 + (v01 - v00) * wx;
        float vb = v10 + (v11 - v10) * wx;
        v[s] = (va + (vb - va) * wy) * LOG2E;
    }
    posb[i] = cvt_bf2(v[1], v[0]);
}

// ============ qkv GEMM: C = w_qkv * x, fused bf16 tile pack =================
__global__ __launch_bounds__(256) void qkv_gemm_kernel(
    const float* __restrict__ A, const float* __restrict__ B,
    uint8_t* __restrict__ tiles, int K)
{
    __shared__ __align__(128) char sA[8192];
    __shared__ __align__(128) char sB[8192];
    __shared__ __align__(16)  float sT[32][132];
    const int t = threadIdx.x, wid = t >> 5, lane = t & 31;
    const int bm = blockIdx.y * 128, bn = blockIdx.x * 128;
    const uint32_t ab = smem_u32(sA), bb = smem_u32(sB);

    const int ma = t >> 1, qa = t & 1;
    const int nb = t & 127, kh = t >> 7;

    const int fr = wid * 16 + (lane & 7) + ((lane >> 3) & 1) * 8;
    const uint32_t aA0 = ab + SW64R(fr * 64 + (lane >> 4) * 16);
    const uint32_t aA1 = ab + SW64R(fr * 64 + (2 + (lane >> 4)) * 16);
    const int br = (lane & 7) + (lane >> 4) * 8;
    const uint32_t aB0 = bb + SW64R(br * 64 + ((lane >> 3) & 1) * 16);
    const uint32_t aB1 = bb + SW64R(br * 64 + (2 + ((lane >> 3) & 1)) * 16);

    const uint32_t stA0 = ab + SW64R(ma * 64 + qa * 32);
    const uint32_t stA1 = ab + SW64R(ma * 64 + qa * 32 + 16);
    const uint32_t stB0 = bb + SW64R(nb * 64 + kh * 32);
    const uint32_t stB1 = bb + SW64R(nb * 64 + kh * 32 + 16);

    float acc[16][4];
    #pragma unroll
    for (int i = 0; i < 16; i++)
        #pragma unroll
        for (int v = 0; v < 4; v++) acc[i][v] = 0.f;

    const int ntiles = K >> 5;
    float av[16], bv[16];

    {
        const float* ap = A + (size_t)(bm + ma) * K + qa * 16;
        #pragma unroll
        for (int i = 0; i < 4; i++) {
            float4 x = ((const float4*)ap)[i];
            av[4*i] = x.x; av[4*i+1] = x.y; av[4*i+2] = x.z; av[4*i+3] = x.w;
        }
        const float* bp = B + (size_t)(kh * 16) * HW + bn + nb;
        #pragma unroll
        for (int i = 0; i < 16; i++) bv[i] = bp[(size_t)i * HW];
        uint32_t ua[8], ub[8];
        #pragma unroll
        for (int i = 0; i < 8; i++) {
            ua[i] = cvt_bf2(av[2*i+1], av[2*i]);
            ub[i] = cvt_bf2(bv[2*i+1], bv[2*i]);
        }
        asm volatile("st.shared.v4.b32 [%0], {%1,%2,%3,%4};"
                     :: "r"(stA0), "r"(ua[0]), "r"(ua[1]), "r"(ua[2]), "r"(ua[3]));
        asm volatile("st.shared.v4.b32 [%0], {%1,%2,%3,%4};"
                     :: "r"(stA1), "r"(ua[4]), "r"(ua[5]), "r"(ua[6]), "r"(ua[7]));
        asm volatile("st.shared.v4.b32 [%0], {%1,%2,%3,%4};"
                     :: "r"(stB0), "r"(ub[0]), "r"(ub[1]), "r"(ub[2]), "r"(ub[3]));
        asm volatile("st.shared.v4.b32 [%0], {%1,%2,%3,%4};"
                     :: "r"(stB1), "r"(ub[4]), "r"(ub[5]), "r"(ub[6]), "r"(ub[7]));
    }
    __syncthreads();

    for (int kt = 0; kt < ntiles; kt++) {
        if (kt + 1 < ntiles) {
            int k0 = (kt + 1) * 32;
            const float* ap = A + (size_t)(bm + ma) * K + k0 + qa * 16;
            #pragma unroll
            for (int i = 0; i < 4; i++) {
                float4 x = ((const float4*)ap)[i];
                av[4*i] = x.x; av[4*i+1] = x.y; av[4*i+2] = x.z; av[4*i+3] = x.w;
            }
            const float* bp = B + (size_t)(k0 + kh * 16) * HW + bn + nb;
            #pragma unroll
            for (int i = 0; i < 16; i++) bv[i] = bp[(size_t)i * HW];
        }

        uint32_t A0[4], A1[4];
        ldsm4(A0[0], A0[1], A0[2], A0[3], aA0);
        ldsm4(A1[0], A1[1], A1[2], A1[3], aA1);
        #pragma unroll
        for (int nch = 0; nch < 8; nch++) {
            uint32_t b00, b01, b02, b03, b10, b11, b12, b13;
            ldsm4(b00, b01, b02, b03, aB0 + nch * 1024);
            ldsm4(b10, b11, b12, b13, aB1 + nch * 1024);
            mma16816(acc[2*nch],   A0, b00, b01);
            mma16816(acc[2*nch],   A1, b10, b11);
            mma16816(acc[2*nch+1], A0, b02, b03);
            mma16816(acc[2*nch+1], A1, b12, b13);
        }
        __syncthreads();
        if (kt + 1 < ntiles) {
            uint32_t ua[8], ub[8];
            #pragma unroll
            for (int i = 0; i < 8; i++) {
                ua[i] = cvt_bf2(av[2*i+1], av[2*i]);
                ub[i] = cvt_bf2(bv[2*i+1], bv[2*i]);
            }
            asm volatile("st.shared.v4.b32 [%0], {%1,%2,%3,%4};"
                         :: "r"(stA0), "r"(ua[0]), "r"(ua[1]), "r"(ua[2]), "r"(ua[3]));
            asm volatile("st.shared.v4.b32 [%0], {%1,%2,%3,%4};"
                         :: "r"(stA1), "r"(ua[4]), "r"(ua[5]), "r"(ua[6]), "r"(ua[7]));
            asm volatile("st.shared.v4.b32 [%0], {%1,%2,%3,%4};"
                         :: "r"(stB0), "r"(ub[0]), "r"(ub[1]), "r"(ub[2]), "r"(ub[3]));
            asm volatile("st.shared.v4.b32 [%0], {%1,%2,%3,%4};"
                         :: "r"(stB1), "r"(ub[4]), "r"(ub[5]), "r"(ub[6]), "r"(ub[7]));
        }
        __syncthreads();
    }

    const int g2 = lane >> 2, q2 = lane & 3;
    const int chA = wid * 16 + g2;
    const int type = bm >> 8;
    const float esc = (type == 0) ? (QSCALE * LOG2E) : 1.0f;
    uint8_t* tbase = tiles + (size_t)(type * 8) * 32 * 8192 + (size_t)blockIdx.x * 8192;

    #pragma unroll
    for (int p0 = 0; p0 < 128; p0 += 32) {
        __syncthreads();
        #pragma unroll
        for (int t2 = 0; t2 < 4; t2++) {
            int nc  = (p0 >> 3) + t2;
            int pxl = nc * 8 + q2 * 2 - p0;
            sT[pxl][chA]         = acc[nc][0];
            sT[pxl + 1][chA]     = acc[nc][1];
            sT[pxl][chA + 8]     = acc[nc][2];
            sT[pxl + 1][chA + 8] = acc[nc][3];
        }
        __syncthreads();
        int pxl = t >> 3;
        int pixrow = p0 + pxl;
        #pragma unroll
        for (int s = 0; s < 2; s++) {
            int w = (t & 7) + s * 8;
            int hh = ((bm & 255) >> 5) + (w >> 2);
            int d0 = (w & 3) * 8;
            float4 f0 = *(float4*)&sT[pxl][w * 8];
            float4 f1 = *(float4*)&sT[pxl][w * 8 + 4];
            uint32_t b0 = cvt_bf2(f0.y * esc, f0.x * esc);
            uint32_t b1 = cvt_bf2(f0.w * esc, f0.z * esc);
            uint32_t b2 = cvt_bf2(f1.y * esc, f1.x * esc);
            uint32_t b3 = cvt_bf2(f1.w * esc, f1.z * esc);
            uint8_t* blob = tbase + (size_t)hh * 32 * 8192;
            *(uint4*)(blob + SW64R(pixrow * 64 + d0 * 2)) = make_uint4(b0, b1, b2, b3);
        }
    }
}

// ====== flash attention, single pass, fused normalize+pack epilogue =========
__global__ __launch_bounds__(128, 4) void attn_kernel(
    const uint8_t* __restrict__ tiles, const uint32_t* __restrict__ posb,
    uint8_t* __restrict__ ytiles)
{
    __shared__ __align__(128) char sQ[8192];
    __shared__ __align__(128) char sK[16384];
    __shared__ __align__(128) char sV[16384];
    __shared__ __align__(16)  char sPos[512];

    const int tid  = threadIdx.x;
    const int wid  = tid >> 5;
    const int lane = tid & 31;
    const int g    = lane >> 2;
    const int c    = lane & 3;
    const int h    = blockIdx.y;

    const uint32_t qb = smem_u32(sQ), kb = smem_u32(sK), vb = smem_u32(sV);
    const uint32_t pbs = smem_u32(sPos);

    const uint8_t* tQ = tiles + (size_t)(h * 32 + blockIdx.x) * 8192;
    const uint8_t* tK = tiles + (size_t)((8 + h) * 32) * 8192;
    const uint8_t* tV = tiles + (size_t)((16 + h) * 32) * 8192;
    const uint8_t* tP = (const uint8_t*)(posb + h * 2048);

    {
        uint32_t o = tid << 4;
        #pragma unroll
        for (int s = 0; s < 4; s++) {
            CP16(qb + o + s * 2048, tQ + o + s * 2048);
            CP16(kb + o + s * 2048, tK + o + s * 2048);
            CP16(vb + o + s * 2048, tV + o + s * 2048);
        }
        if (tid < 16) CP16(pbs + (tid << 4), tP + (tid << 4));
        CPCOMMIT();
        CPWAIT0();
    }
    __syncthreads();

    uint32_t QAa0[4], QAa1[4], QAb0[4], QAb1[4];
    {
        int rowa = wid * 32 + (lane & 7) + ((lane >> 3) & 1) * 8;
        int ch   = lane >> 4;
        ldsm4(QAa0[0], QAa0[1], QAa0[2], QAa0[3], qb + SW64R(rowa * 64 + ch * 16));
        ldsm4(QAa1[0], QAa1[1], QAa1[2], QAa1[3], qb + SW64R(rowa * 64 + (2 + ch) * 16));
        int rowb = rowa + 16;
        ldsm4(QAb0[0], QAb0[1], QAb0[2], QAb0[3], qb + SW64R(rowb * 64 + ch * 16));
        ldsm4(QAb1[0], QAb1[1], QAb1[2], QAb1[3], qb + SW64R(rowb * 64 + (2 + ch) * 16));
    }
    uint32_t aK0, aK1, aV0, aV1;
    {
        int ko = (lane & 7) + (lane >> 4) * 8;
        int ch = (lane >> 3) & 1;
        aK0 = kb + SW64R(ko * 64 + ch * 16);
        aK1 = kb + SW64R(ko * 64 + (2 + ch) * 16);
    }
    {
        int ko = (lane & 7) + ((lane >> 3) & 1) * 8;
        int ch = lane >> 4;
        aV0 = vb + SW64R(ko * 64 + ch * 16);
        aV1 = vb + SW64R(ko * 64 + (2 + ch) * 16);
    }

    const uint32_t bOne = (lane < 4) ? 0x3F803F80u : 0u;
    float Ya[4][4], Yb[4][4], Ysa[4], Ysb[4];
    #pragma unroll
    for (int u = 0; u < 4; u++) {
        Ysa[u] = 0.f; Ysb[u] = 0.f;
        #pragma unroll
        for (int v = 0; v < 4; v++) { Ya[u][v] = 0.f; Yb[u][v] = 0.f; }
    }

    uint32_t kf[2][8];

    for (int it = 0; it < 32; it++) {
        const uint32_t bofs = (uint32_t)(it & 1) * 8192;

        if (it < 31) {
            const uint32_t nofs = (uint32_t)((it + 1) & 1) * 8192;
            const size_t jo = (size_t)(it + 1) * 8192;
            uint32_t o = tid << 4;
            #pragma unroll
            for (int s = 0; s < 4; s++) {
                CP16(kb + nofs + o + s * 2048, tK + jo + o + s * 2048);
                CP16(vb + nofs + o + s * 2048, tV + jo + o + s * 2048);
            }
            if (tid < 16)
                CP16(pbs + (((it + 1) & 1) << 8) + (tid << 4),
                     tP + (size_t)(it + 1) * 256 + (tid << 4));
            CPCOMMIT();
        }

        const uint32_t kA0 = aK0 + bofs, kA1 = aK1 + bofs;
        const uint32_t vA0 = aV0 + bofs, vA1 = aV1 + bofs;
        const uint32_t* sp = (const uint32_t*)(sPos + (it & 1) * 256);

        ldsm4(kf[0][0], kf[0][1], kf[0][2], kf[0][3], kA0);
        ldsm4(kf[0][4], kf[0][5], kf[0][6], kf[0][7], kA1);

        #pragma unroll
        for (int j = 0; j < 8; j++) {
            const uint32_t* kc = kf[j & 1];
            uint32_t* kn = kf[(j + 1) & 1];

            uint32_t pos0 = sp[j * 8 + c];
            uint32_t pos1 = sp[j * 8 + 4 + c];

            uint32_t v0, v1, v2, v3, w0, w1, w2, w3;
            ldsm4t(v0, v1, v2, v3, vA0 + j * 1024);
            ldsm4t(w0, w1, w2, w3, vA1 + j * 1024);
            if (j < 7) {
                ldsm4(kn[0], kn[1], kn[2], kn[3], kA0 + (j + 1) * 1024);
                ldsm4(kn[4], kn[5], kn[6], kn[7], kA1 + (j + 1) * 1024);
            }

            float Ca0[4] = {0.f,0.f,0.f,0.f}, Ca1[4] = {0.f,0.f,0.f,0.f};
            float Cb0[4] = {0.f,0.f,0.f,0.f}, Cb1[4] = {0.f,0.f,0.f,0.f};
            mma16816(Ca0, QAa0, kc[0], kc[1]);
            mma16816(Ca0, QAa1, kc[4], kc[5]);
            mma16816(Ca1, QAa0, kc[2], kc[3]);
            mma16816(Ca1, QAa1, kc[6], kc[7]);
            mma16816(Cb0, QAb0, kc[0], kc[1]);
            mma16816(Cb0, QAb1, kc[4], kc[5]);
            mma16816(Cb1, QAb0, kc[2], kc[3]);
            mma16816(Cb1, QAb1, kc[6], kc[7]);

            uint32_t Pa[4], Pb[4];
            Pa[0] = pexp2(cvt_bf2(Ca0[1], Ca0[0]), pos0);
            Pa[1] = pexp2(cvt_bf2(Ca0[3], Ca0[2]), pos0);
            Pa[2] = pexp2(cvt_bf2(Ca1[1], Ca1[0]), pos1);
            Pa[3] = pexp2(cvt_bf2(Ca1[3], Ca1[2]), pos1);
            Pb[0] = pexp2(cvt_bf2(Cb0[1], Cb0[0]), pos0);
            Pb[1] = pexp2(cvt_bf2(Cb0[3], Cb0[2]), pos0);
            Pb[2] = pexp2(cvt_bf2(Cb1[1], Cb1[0]), pos1);
            Pb[3] = pexp2(cvt_bf2(Cb1[3], Cb1[2]), pos1);

            mma16816(Ya[0], Pa, v0, v1);
            mma16816(Ya[1], Pa, v2, v3);
            mma16816(Ya[2], Pa, w0, w1);
            mma16816(Ya[3], Pa, w2, w3);
            mma16816(Ysa,   Pa, bOne, bOne);
            mma16816(Yb[0], Pb, v0, v1);
            mma16816(Yb[1], Pb, v2, v3);
            mma16816(Yb[2], Pb, w0, w1);
            mma16816(Yb[3], Pb, w2, w3);
            mma16816(Ysb,   Pb, bOne, bOne);
        }

        if (it < 31) CPWAIT0();
        __syncthreads();
    }

    // ---- fused epilogue: normalize, transpose via sK overlay, pack tiles ----
    float iAa = 1.f / __shfl_sync(0xffffffffu, Ysa[0], lane & 28);
    float iBa = 1.f / __shfl_sync(0xffffffffu, Ysa[2], lane & 28);
    float iAb = 1.f / __shfl_sync(0xffffffffu, Ysb[0], lane & 28);
    float iBb = 1.f / __shfl_sync(0xffffffffu, Ysb[2], lane & 28);

    float* sT = (float*)sK;
    uint8_t* blob = ytiles + (size_t)(h * 32 + blockIdx.x) * 8192;
    const int rla = (wid & 1) * 32 + g;

    #pragma unroll
    for (int pass = 0; pass < 2; pass++) {
        if ((wid >> 1) == pass) {
            #pragma unroll
            for (int v = 0; v < 4; v++) {
                int ch = v * 8 + 2 * c;
                sT[rla * 33 + ch]            = Ya[v][0] * iAa;
                sT[rla * 33 + ch + 1]        = Ya[v][1] * iAa;
                sT[(rla + 8) * 33 + ch]      = Ya[v][2] * iBa;
                sT[(rla + 8) * 33 + ch + 1]  = Ya[v][3] * iBa;
                sT[(rla + 16) * 33 + ch]     = Yb[v][0] * iAb;
                sT[(rla + 16) * 33 + ch + 1] = Yb[v][1] * iAb;
                sT[(rla + 24) * 33 + ch]     = Yb[v][2] * iBb;
                sT[(rla + 24) * 33 + ch + 1] = Yb[v][3] * iBb;
            }
        }
        __syncthreads();
        {
            int pr   = tid >> 1;
            int half = tid & 1;
            int pix  = pass * 64 + pr;
            const float* row = sT + pr * 33 + half * 16;
            uint32_t b[8];
            #pragma unroll
            for (int i = 0; i < 8; i++)
                b[i] = cvt_bf2(row[2*i + 1], row[2*i]);
            *(uint4*)(blob + SW64R(pix * 64 + half * 32)) =
                make_uint4(b[0], b[1], b[2], b[3]);
            *(uint4*)(blob + SW64R(pix * 64 + half * 32 + 16)) =
                make_uint4(b[4], b[5], b[6], b[7]);
        }
        __syncthreads();
    }
}

// ===== proj GEMM: ALL B blobs staged once (64KB dyn smem), waitless loop ====
#define PROJ_SMEM (8192 + 65536 + 128)
__global__ __launch_bounds__(256) void proj_gemm_kernel(
    const float* __restrict__ A, const uint8_t* __restrict__ ytiles,
    const float* __restrict__ bias, float* __restrict__ C)
{
    extern __shared__ char dyn[];
    char* sm = (char*)(((uintptr_t)dyn + 127) & ~(uintptr_t)127);
    char* sA = sm;                 // 8KB
    char* sB = sm + 8192;          // 64KB (8 blobs)

    const int t = threadIdx.x, wid = t >> 5, lane = t & 31;
    const int bm = blockIdx.y * 128, bn = blockIdx.x * 128;
    const int K = 256, N = HW;
    const uint32_t ab = smem_u32(sA), bb = smem_u32(sB);

    const int ma = t >> 1, qa = t & 1;

    const int fr = wid * 16 + (lane & 7) + ((lane >> 3) & 1) * 8;
    const uint32_t aA0 = ab + SW64R(fr * 64 + (lane >> 4) * 16);
    const uint32_t aA1 = ab + SW64R(fr * 64 + (2 + (lane >> 4)) * 16);
    const int br = (lane & 7) + (lane >> 4) * 8;
    const uint32_t aB0 = bb + SW64R(br * 64 + ((lane >> 3) & 1) * 16);
    const uint32_t aB1 = bb + SW64R(br * 64 + (2 + ((lane >> 3) & 1)) * 16);

    const uint32_t stA0 = ab + SW64R(ma * 64 + qa * 32);
    const uint32_t stA1 = ab + SW64R(ma * 64 + qa * 32 + 16);

    const uint8_t* ybase = ytiles + (size_t)blockIdx.x * 8192;

    float acc[16][4];
    #pragma unroll
    for (int i = 0; i < 16; i++)
        #pragma unroll
        for (int v = 0; v < 4; v++) acc[i][v] = 0.f;

    float av[16];

    // prologue: ALL B blobs via cp.async (MLP-overlapped), A0 staged
    {
        uint32_t o = t << 4;
        #pragma unroll
        for (int kt = 0; kt < 8; kt++) {
            const uint8_t* src = ybase + (size_t)kt * 32 * 8192;
            CP16(bb + kt * 8192 + o,        src + o);
            CP16(bb + kt * 8192 + o + 4096, src + o + 4096);
        }
        CPCOMMIT();
        const float* ap = A + (size_t)(bm + ma) * K + qa * 16;
        #pragma unroll
        for (int i = 0; i < 4; i++) {
            float4 x = ((const float4*)ap)[i];
            av[4*i] = x.x; av[4*i+1] = x.y; av[4*i+2] = x.z; av[4*i+3] = x.w;
        }
        uint32_t ua[8];
        #pragma unroll
        for (int i = 0; i < 8; i++) ua[i] = cvt_bf2(av[2*i+1], av[2*i]);
        asm volatile("st.shared.v4.b32 [%0], {%1,%2,%3,%4};"
                     :: "r"(stA0), "r"(ua[0]), "r"(ua[1]), "r"(ua[2]), "r"(ua[3]));
        asm volatile("st.shared.v4.b32 [%0], {%1,%2,%3,%4};"
                     :: "r"(stA1), "r"(ua[4]), "r"(ua[5]), "r"(ua[6]), "r"(ua[7]));
        CPWAIT0();
    }
    __syncthreads();

    for (int kt = 0; kt < 8; kt++) {
        if (kt < 7) {
            const float* ap = A + (size_t)(bm + ma) * K + (kt + 1) * 32 + qa * 16;
            #pragma unroll
            for (int i = 0; i < 4; i++) {
                float4 x = ((const float4*)ap)[i];
                av[4*i] = x.x; av[4*i+1] = x.y; av[4*i+2] = x.z; av[4*i+3] = x.w;
            }
        }

        const uint32_t bofs = (uint32_t)kt * 8192;
        uint32_t A0[4], A1[4];
        ldsm4(A0[0], A0[1], A0[2], A0[3], aA0);
        ldsm4(A1[0], A1[1], A1[2], A1[3], aA1);
        #pragma unroll
        for (int nch = 0; nch < 8; nch++) {
            uint32_t b00, b01, b02, b03, b10, b11, b12, b13;
            ldsm4(b00, b01, b02, b03, aB0 + bofs + nch * 1024);
            ldsm4(b10, b11, b12, b13, aB1 + bofs + nch * 1024);
            mma16816(acc[2*nch],   A0, b00, b01);
            mma16816(acc[2*nch],   A1, b10, b11);
            mma16816(acc[2*nch+1], A0, b02, b03);
            mma16816(acc[2*nch+1], A1, b12, b13);
        }
        __syncthreads();
        if (kt < 7) {
            uint32_t ua[8];
            #pragma unroll
            for (int i = 0; i < 8; i++) ua[i] = cvt_bf2(av[2*i+1], av[2*i]);
            asm volatile("st.shared.v4.b32 [%0], {%1,%2,%3,%4};"
                         :: "r"(stA0), "r"(ua[0]), "r"(ua[1]), "r"(ua[2]), "r"(ua[3]));
            asm volatile("st.shared.v4.b32 [%0], {%1,%2,%3,%4};"
                         :: "r"(stA1), "r"(ua[4]), "r"(ua[5]), "r"(ua[6]), "r"(ua[7]));
        }
        __syncthreads();
    }

    int r0 = bm + wid * 16 + (lane >> 2);
    float bv0 = bias[r0];
    float bv1 = bias[r0 + 8];
    float* c0p = C + (size_t)r0 * N + bn + (lane & 3) * 2;
    float* c1p = C + (size_t)(r0 + 8) * N + bn + (lane & 3) * 2;
    #pragma unroll
    for (int nc = 0; nc < 16; nc++) {
        *(float2*)(c0p + nc * 8) = make_float2(acc[nc][0] + bv0, acc[nc][1] + bv0);
        *(float2*)(c1p + nc * 8) = make_float2(acc[nc][2] + bv1, acc[nc][3] + bv1);
    }
}

// ------- residual + channel LayerNorm: 256 CTAs, 16 px x 16 groups ----------
__global__ __launch_bounds__(256) void ln_kernel(
    const float* __restrict__ x, const float* __restrict__ yp,
    const float* __restrict__ gamma, const float* __restrict__ beta,
    float* __restrict__ out)
{
    __shared__ float ssum[16][16], ssq[16][16];
    int nx = threadIdx.x & 15;
    int cg = threadIdx.x >> 4;
    int n  = blockIdx.x * 16 + nx;

    float z[32];
    float sum = 0.f, sq = 0.f;
    #pragma unroll
    for (int i = 0; i < 32; i++) {
        int c = cg + i * 16;
        z[i] = x[(size_t)c * HW + n] + yp[(size_t)c * HW + n];
        sum += z[i]; sq += z[i] * z[i];
    }
    ssum[cg][nx] = sum; ssq[cg][nx] = sq;
    __syncthreads();
    float tot = 0.f, totsq = 0.f;
    #pragma unroll
    for (int g = 0; g < 16; g++) { tot += ssum[g][nx]; totsq += ssq[g][nx]; }
    float mu   = tot * (1.f / 512.f);
    float var  = totsq * (1.f / 512.f) - mu * mu;
    float rstd = rsqrtf(var + 1e-5f);
    #pragma unroll
    for (int i = 0; i < 32; i++) {
        int c = cg + i * 16;
        out[(size_t)c * HW + n] = (z[i] - mu) * rstd * gamma[c] + beta[c];
    }
}

// -----------------------------------------------------------------------------
extern "C" void kernel_launch(void* const* d_in, const int* in_sizes, int n_in,
                              void* d_out, int out_size) {
    const float* x        = (const float*)d_in[0];
    const float* w_qkv    = (const float*)d_in[1];
    const float* w_proj   = (const float*)d_in[2];
    const float* b_proj   = (const float*)d_in[3];
    const float* pos_bias = (const float*)d_in[4];
    const float* gamma    = (const float*)d_in[5];
    const float* beta     = (const float*)d_in[6];
    float* out = (float*)d_out;

    float* proj;
    uint8_t *tiles, *ytiles;
    uint32_t* posb;
    cudaGetSymbolAddress((void**)&proj,   g_proj);
    cudaGetSymbolAddress((void**)&tiles,  g_tiles);
    cudaGetSymbolAddress((void**)&ytiles, g_ytiles);
    cudaGetSymbolAddress((void**)&posb,   g_posb);

    cudaFuncSetAttribute(proj_gemm_kernel,
                         cudaFuncAttributeMaxDynamicSharedMemorySize, PROJ_SMEM);

    pos_kernel<<<64, 256>>>(pos_bias, posb);
    qkv_gemm_kernel<<<dim3(32, 6), 256>>>(w_qkv, x, tiles, 512);
    attn_kernel<<<dim3(32, 8), 128>>>(tiles, posb, ytiles);
    proj_gemm_kernel<<<dim3(32, 4), 256, PROJ_SMEM>>>(w_proj, ytiles, b_proj, proj);
    ln_kernel<<<256, 256>>>(x, proj, gamma, beta, out);
}